// round 4
// baseline (speedup 1.0000x reference)
#include <cuda_runtime.h>
#include <cstdint>

// ---------------- problem constants ----------------
#define FEA      64
#define NTOT     14112
#define COST_IDX (NTOT * FEA)               /* 903168 */
#define INV_CNT  (1.0f / (14112.0f * 4096.0f))

// W b-fragments, hi/lo bf16x2, layout [ks][lane][nt*2+r] (2048 u32 each)
__device__ unsigned g_Bfh[2048];
__device__ unsigned g_Bfl[2048];

// ---------------- helpers ----------------
// split (x,y) into packed bf16x2 hi (lo16=x) + bf16x2 lo residual
__device__ __forceinline__ void cvtpair(float x, float y, uint32_t& h, uint32_t& l) {
    asm("cvt.rn.bf16x2.f32 %0, %1, %2;" : "=r"(h) : "f"(y), "f"(x));
    float hx = __uint_as_float(h << 16);
    float hy = __uint_as_float(h & 0xffff0000u);
    float lx = x - hx, ly = y - hy;
    asm("cvt.rn.bf16x2.f32 %0, %1, %2;" : "=r"(l) : "f"(ly), "f"(lx));
}

#define MMA_BF16(d, a, b) \
    asm volatile("mma.sync.aligned.m16n8k16.row.col.f32.bf16.bf16.f32 " \
                 "{%0,%1,%2,%3},{%4,%5,%6,%7},{%8,%9},{%0,%1,%2,%3};" \
                 : "+f"((d)[0]), "+f"((d)[1]), "+f"((d)[2]), "+f"((d)[3]) \
                 : "r"((a)[0]), "r"((a)[1]), "r"((a)[2]), "r"((a)[3]), \
                   "r"((b)[0]), "r"((b)[1]))

// ---------------- prep: W -> b-fragment tables, zero cost slot -------------
__global__ void ot_prep_kernel(const float* __restrict__ W,
                               float* __restrict__ out, int out_size) {
    int t = blockIdx.x * blockDim.x + threadIdx.x;   // 0..2047
    if (t < 2048) {
        int ks   = t >> 9;
        int lane = (t >> 4) & 31;
        int idx  = t & 15;            // nt*2 + r
        int nt   = idx >> 1;
        int r    = idx & 1;
        int nn   = (lane >> 2) + 8 * nt;              // B col (output h)
        int k    = ((lane & 3) << 1) + 16 * ks + 8 * r;
        uint32_t h, l;
        cvtpair(W[nn * 64 + k], W[nn * 64 + k + 1], h, l);
        g_Bfh[t] = h;
        g_Bfl[t] = l;
    }
    if (t == 0)
        for (int i = COST_IDX; i < out_size; ++i) out[i] = 0.0f;
}

// ---------------- main kernel: 1 CTA / problem, register-resident ----------
__global__ void __launch_bounds__(128)
ot_mma_kernel(const float* __restrict__ x, const float* __restrict__ P,
              const float* __restrict__ mask, const float* __restrict__ bias,
              const float* __restrict__ gamma, const float* __restrict__ beta,
              float* __restrict__ out, int out_size) {

    __shared__ float txbuf[4][64];
    __shared__ float cred[4];

    const int n    = blockIdx.x;
    const int tid  = threadIdx.x;
    const int lane = tid & 31;
    const int wid  = tid >> 5;
    const int q    = lane >> 2;          // group id 0..7
    const int tg   = lane & 3;           // thread-in-group
    const int c2   = tg << 1;            // col pair base

    // n -> (b, v, p); x/out row base
    const int bb = n / (21 * 42);
    const int rm = n - bb * (21 * 42);
    const int vv = rm / 42;
    const int pp = rm - vv * 42;
    const size_t xob = ((size_t)(bb * 42 + pp) * 21 + vv) * FEA;

    const int fA = 16 * wid + q;         // this thread's two M rows
    const int fB = fA + 8;

    // ---- A fragments: direct LDG from P + hi/lo split in registers ----
    const float2* P2 = (const float2*)(P + ((size_t)n << 12));
    uint32_t ahA[8], alA[8], ahB[8], alB[8];   // j = col-octet index
    {
        const int baseA = fA * 32 + tg;
        const int baseB = fB * 32 + tg;
#pragma unroll
        for (int j = 0; j < 8; ++j) {
            float2 ua = P2[baseA + 4 * j];
            float2 ub = P2[baseB + 4 * j];
            cvtpair(ua.x, ua.y, ahA[j], alA[j]);
            cvtpair(ub.x, ub.y, ahB[j], alB[j]);
        }
    }

    // ---- GEMM: 96 HMMA, B streamed per k-step from fragment table ----
    float acc[8][4];
#pragma unroll
    for (int nt = 0; nt < 8; ++nt)
#pragma unroll
        for (int j = 0; j < 4; ++j) acc[nt][j] = 0.f;

#pragma unroll
    for (int ks = 0; ks < 4; ++ks) {
        uint4 bh4[4], bl4[4];
        const uint4* bp = ((const uint4*)g_Bfh) + (((ks << 5) + lane) << 2);
        const uint4* lp = ((const uint4*)g_Bfl) + (((ks << 5) + lane) << 2);
#pragma unroll
        for (int i = 0; i < 4; ++i) { bh4[i] = bp[i]; bl4[i] = lp[i]; }
        const uint32_t* bhw = (const uint32_t*)bh4;
        const uint32_t* blw = (const uint32_t*)bl4;

        uint32_t ah[4] = { ahA[2*ks], ahB[2*ks], ahA[2*ks+1], ahB[2*ks+1] };
        uint32_t al[4] = { alA[2*ks], alB[2*ks], alA[2*ks+1], alB[2*ks+1] };

#pragma unroll
        for (int nt = 0; nt < 8; ++nt) {
            uint32_t bfh[2] = { bhw[2*nt], bhw[2*nt+1] };
            uint32_t bfl[2] = { blw[2*nt], blw[2*nt+1] };
            MMA_BF16(acc[nt], ah, bfh);   // Phi * Whi
            MMA_BF16(acc[nt], al, bfh);   // Plo * Whi
            MMA_BF16(acc[nt], ah, bfl);   // Phi * Wlo
        }
    }

    // ---- per-column params (cols c2+8nt + {0,1}) ----
    float2 bias2[8], gam2[8], bet2[8], ms2[8];
    {
        const float2* b2 = (const float2*)bias;
        const float2* g2 = (const float2*)gamma;
        const float2* e2 = (const float2*)beta;
        const float2* m2 = (const float2*)(mask + (size_t)n * FEA);
#pragma unroll
        for (int nt = 0; nt < 8; ++nt) {
            int ix = 4 * nt + tg;
            bias2[nt] = b2[ix]; gam2[nt] = g2[ix];
            bet2[nt]  = e2[ix]; ms2[nt]  = m2[ix];
        }
    }
    const float xfA = x[xob + fA];
    const float xfB = x[xob + fB];

    // ---- bias + LN stats (rows fA, fB live in this quad) ----
    float vA[16], vB[16];
    float s1A = 0.f, s2A = 0.f, s1B = 0.f, s2B = 0.f;
#pragma unroll
    for (int nt = 0; nt < 8; ++nt) {
        float a0 = acc[nt][0] + bias2[nt].x;
        float a1 = acc[nt][1] + bias2[nt].y;
        float b0 = acc[nt][2] + bias2[nt].x;
        float b1 = acc[nt][3] + bias2[nt].y;
        vA[2*nt] = a0; vA[2*nt+1] = a1;
        vB[2*nt] = b0; vB[2*nt+1] = b1;
        s1A += a0 + a1; s2A += a0*a0 + a1*a1;
        s1B += b0 + b1; s2B += b0*b0 + b1*b1;
    }
#pragma unroll
    for (int m = 1; m <= 2; m <<= 1) {
        s1A += __shfl_xor_sync(0xffffffffu, s1A, m);
        s2A += __shfl_xor_sync(0xffffffffu, s2A, m);
        s1B += __shfl_xor_sync(0xffffffffu, s1B, m);
        s2B += __shfl_xor_sync(0xffffffffu, s2B, m);
    }
    const float muA = s1A * (1.0f/64.0f);
    const float muB = s1B * (1.0f/64.0f);
    const float rsA = rsqrtf(s2A * (1.0f/64.0f) - muA*muA + 1e-5f);
    const float rsB = rsqrtf(s2B * (1.0f/64.0f) - muB*muB + 1e-5f);

    // ---- LN affine + row max ----
    float mxA = -3.4e38f, mxB = -3.4e38f;
#pragma unroll
    for (int nt = 0; nt < 8; ++nt) {
        float zA0 = (vA[2*nt]   - muA) * rsA * gam2[nt].x + bet2[nt].x;
        float zA1 = (vA[2*nt+1] - muA) * rsA * gam2[nt].y + bet2[nt].y;
        float zB0 = (vB[2*nt]   - muB) * rsB * gam2[nt].x + bet2[nt].x;
        float zB1 = (vB[2*nt+1] - muB) * rsB * gam2[nt].y + bet2[nt].y;
        vA[2*nt] = zA0; vA[2*nt+1] = zA1;
        vB[2*nt] = zB0; vB[2*nt+1] = zB1;
        mxA = fmaxf(mxA, fmaxf(zA0, zA1));
        mxB = fmaxf(mxB, fmaxf(zB0, zB1));
    }
#pragma unroll
    for (int m = 1; m <= 2; m <<= 1) {
        mxA = fmaxf(mxA, __shfl_xor_sync(0xffffffffu, mxA, m));
        mxB = fmaxf(mxB, __shfl_xor_sync(0xffffffffu, mxB, m));
    }

    // ---- exp + row sum ----
    float sA = 0.f, sB = 0.f;
#pragma unroll
    for (int i = 0; i < 16; ++i) {
        float eA = __expf(vA[i] - mxA);
        float eB = __expf(vB[i] - mxB);
        vA[i] = eA; vB[i] = eB;
        sA += eA; sB += eB;
    }
#pragma unroll
    for (int m = 1; m <= 2; m <<= 1) {
        sA += __shfl_xor_sync(0xffffffffu, sA, m);
        sB += __shfl_xor_sync(0xffffffffu, sB, m);
    }
    const float invA = __fdividef(1.0f, sA);
    const float invB = __fdividef(1.0f, sB);

    // ---- normalize, cost dot, transport partials ----
    float costp = 0.f;
    float t[16];
#pragma unroll
    for (int nt = 0; nt < 8; ++nt) {
        float pA0 = vA[2*nt]   * invA, pA1 = vA[2*nt+1] * invA;
        float pB0 = vB[2*nt]   * invB, pB1 = vB[2*nt+1] * invB;
        costp += pA0 * ms2[nt].x + pA1 * ms2[nt].y
               + pB0 * ms2[nt].x + pB1 * ms2[nt].y;
        t[2*nt]   = xfA * pA0 + xfB * pB0;
        t[2*nt+1] = xfA * pA1 + xfB * pB1;
    }

    // ---- transport: reduce across the 8 quads (rows of this warp) ----
#pragma unroll
    for (int m = 4; m <= 16; m <<= 1)
#pragma unroll
        for (int i = 0; i < 16; ++i)
            t[i] += __shfl_xor_sync(0xffffffffu, t[i], m);
    if (q == 0) {
#pragma unroll
        for (int nt = 0; nt < 8; ++nt)
            *(float2*)&txbuf[wid][8*nt + c2] = make_float2(t[2*nt], t[2*nt+1]);
    }

    // ---- cost warp reduce ----
#pragma unroll
    for (int m = 1; m <= 16; m <<= 1)
        costp += __shfl_xor_sync(0xffffffffu, costp, m);
    if (lane == 0) cred[wid] = costp;
    __syncthreads();

    // ---- combine warps: output row + cost atomic ----
    if (tid < FEA)
        out[xob + tid] = (txbuf[0][tid] + txbuf[1][tid])
                       + (txbuf[2][tid] + txbuf[3][tid]);
    if (tid == 0 && out_size > COST_IDX)
        atomicAdd(&out[COST_IDX], (cred[0] + cred[1] + cred[2] + cred[3]) * INV_CNT);
}

extern "C" void kernel_launch(void* const* d_in, const int* in_sizes, int n_in,
                              void* d_out, int out_size) {
    const float* x     = (const float*)d_in[0];
    const float* P     = (const float*)d_in[1];
    const float* mask  = (const float*)d_in[2];
    const float* W     = (const float*)d_in[3];
    const float* bias  = (const float*)d_in[4];
    const float* gamma = (const float*)d_in[5];
    const float* beta  = (const float*)d_in[6];
    float* out = (float*)d_out;

    ot_prep_kernel<<<8, 256>>>(W, out, out_size);
    ot_mma_kernel<<<NTOT, 128>>>(x, P, mask, bias, gamma, beta, out, out_size);
}

// round 5
// speedup vs baseline: 1.7052x; 1.7052x over previous
#include <cuda_runtime.h>
#include <cstdint>

// ---------------- problem constants ----------------
#define FEA      64
#define NTOT     14112
#define COST_IDX (NTOT * FEA)               /* 903168 */
#define INV_CNT  (1.0f / (14112.0f * 4096.0f))

// W b-fragments, hi/lo bf16x2.
// Layout: flat u32 index t = ((i*4 + ks)*32 + lane)*4 + w   (i,ks<4, lane<32, w<4)
// so the 4 uint4 loads per (ks,lane) are lane-consecutive -> coalesced.
// Word (i,w) holds fragment slot idx16 = i*4+w = nt*2+r (same contents as R4).
__device__ unsigned g_Bfh[2048];
__device__ unsigned g_Bfl[2048];

// ---------------- helpers ----------------
// split (x,y) into packed bf16x2 hi (lo16=x) + bf16x2 lo residual
__device__ __forceinline__ void cvtpair(float x, float y, uint32_t& h, uint32_t& l) {
    asm("cvt.rn.bf16x2.f32 %0, %1, %2;" : "=r"(h) : "f"(y), "f"(x));
    float hx = __uint_as_float(h << 16);
    float hy = __uint_as_float(h & 0xffff0000u);
    float lx = x - hx, ly = y - hy;
    asm("cvt.rn.bf16x2.f32 %0, %1, %2;" : "=r"(l) : "f"(ly), "f"(lx));
}

#define MMA_BF16(d, a, b) \
    asm volatile("mma.sync.aligned.m16n8k16.row.col.f32.bf16.bf16.f32 " \
                 "{%0,%1,%2,%3},{%4,%5,%6,%7},{%8,%9},{%0,%1,%2,%3};" \
                 : "+f"((d)[0]), "+f"((d)[1]), "+f"((d)[2]), "+f"((d)[3]) \
                 : "r"((a)[0]), "r"((a)[1]), "r"((a)[2]), "r"((a)[3]), \
                   "r"((b)[0]), "r"((b)[1]))

// ---------------- prep: W -> b-fragment tables, zero cost slot -------------
__global__ void ot_prep_kernel(const float* __restrict__ W,
                               float* __restrict__ out, int out_size) {
    int t = blockIdx.x * blockDim.x + threadIdx.x;   // 0..2047
    if (t < 2048) {
        int w    = t & 3;
        int lane = (t >> 2) & 31;
        int ks   = (t >> 7) & 3;
        int i    = t >> 9;
        int idx16 = i * 4 + w;        // nt*2 + r
        int nt   = idx16 >> 1;
        int r    = idx16 & 1;
        int nn   = (lane >> 2) + 8 * nt;              // B col (output h)
        int k    = ((lane & 3) << 1) + 16 * ks + 8 * r;
        uint32_t h, l;
        cvtpair(W[nn * 64 + k], W[nn * 64 + k + 1], h, l);
        g_Bfh[t] = h;
        g_Bfl[t] = l;
    }
    if (t == 0)
        for (int i = COST_IDX; i < out_size; ++i) out[i] = 0.0f;
}

// ---------------- main kernel: 1 CTA / problem, register-resident ----------
__global__ void __launch_bounds__(128)
ot_mma_kernel(const float* __restrict__ x, const float* __restrict__ P,
              const float* __restrict__ mask, const float* __restrict__ bias,
              const float* __restrict__ gamma, const float* __restrict__ beta,
              float* __restrict__ out, int out_size) {

    __shared__ float txbuf[4][64];
    __shared__ float cred[4];

    const int n    = blockIdx.x;
    const int tid  = threadIdx.x;
    const int lane = tid & 31;
    const int wid  = tid >> 5;
    const int q    = lane >> 2;          // group id 0..7
    const int tg   = lane & 3;           // thread-in-group
    const int c2   = tg << 1;            // col pair base

    // n -> (b, v, p); x/out row base
    const int bb = n / (21 * 42);
    const int rm = n - bb * (21 * 42);
    const int vv = rm / 42;
    const int pp = rm - vv * 42;
    const size_t xob = ((size_t)(bb * 42 + pp) * 21 + vv) * FEA;

    const int fA = 16 * wid + q;         // this thread's two M rows
    const int fB = fA + 8;

    // ---- hoisted DRAM-latency loads: x row values + mask row ----
    const float xfA = x[xob + fA];
    const float xfB = x[xob + fB];
    float2 ms2[8];
    {
        const float2* m2 = (const float2*)(mask + (size_t)n * FEA);
#pragma unroll
        for (int nt = 0; nt < 8; ++nt) ms2[nt] = m2[4 * nt + tg];
    }

    // ---- A fragments: direct LDG from P + hi/lo split in registers ----
    const float2* P2 = (const float2*)(P + ((size_t)n << 12));
    uint32_t ahA[8], alA[8], ahB[8], alB[8];   // j = col-octet index
    {
        const int baseA = fA * 32 + tg;
        const int baseB = fB * 32 + tg;
#pragma unroll
        for (int j = 0; j < 8; ++j) {
            float2 ua = P2[baseA + 4 * j];
            float2 ub = P2[baseB + 4 * j];
            cvtpair(ua.x, ua.y, ahA[j], alA[j]);
            cvtpair(ub.x, ub.y, ahB[j], alB[j]);
        }
    }

    // ---- GEMM: 96 HMMA, B streamed per k-step (coalesced table) ----
    float acc[8][4];
#pragma unroll
    for (int nt = 0; nt < 8; ++nt)
#pragma unroll
        for (int j = 0; j < 4; ++j) acc[nt][j] = 0.f;

#pragma unroll
    for (int ks = 0; ks < 4; ++ks) {
        uint4 bh4[4], bl4[4];
#pragma unroll
        for (int i = 0; i < 4; ++i) {
            int u4idx = (i * 4 + ks) * 32 + lane;      // lane-consecutive
            bh4[i] = ((const uint4*)g_Bfh)[u4idx];
            bl4[i] = ((const uint4*)g_Bfl)[u4idx];
        }
        const uint32_t* bhw = (const uint32_t*)bh4;
        const uint32_t* blw = (const uint32_t*)bl4;

        uint32_t ah[4] = { ahA[2*ks], ahB[2*ks], ahA[2*ks+1], ahB[2*ks+1] };
        uint32_t al[4] = { alA[2*ks], alB[2*ks], alA[2*ks+1], alB[2*ks+1] };

#pragma unroll
        for (int nt = 0; nt < 8; ++nt) {
            uint32_t bfh[2] = { bhw[2*nt], bhw[2*nt+1] };
            uint32_t bfl[2] = { blw[2*nt], blw[2*nt+1] };
            MMA_BF16(acc[nt], ah, bfh);   // Phi * Whi
            MMA_BF16(acc[nt], al, bfh);   // Plo * Whi
            MMA_BF16(acc[nt], ah, bfl);   // Phi * Wlo
        }
    }

    // ---- per-column params (L1/L2-hot, short latency) ----
    float2 bias2[8], gam2[8], bet2[8];
    {
        const float2* b2 = (const float2*)bias;
        const float2* g2 = (const float2*)gamma;
        const float2* e2 = (const float2*)beta;
#pragma unroll
        for (int nt = 0; nt < 8; ++nt) {
            int ix = 4 * nt + tg;
            bias2[nt] = b2[ix]; gam2[nt] = g2[ix]; bet2[nt] = e2[ix];
        }
    }

    // ---- bias + LN stats (rows fA, fB live in this quad) ----
    float vA[16], vB[16];
    float s1A = 0.f, s2A = 0.f, s1B = 0.f, s2B = 0.f;
#pragma unroll
    for (int nt = 0; nt < 8; ++nt) {
        float a0 = acc[nt][0] + bias2[nt].x;
        float a1 = acc[nt][1] + bias2[nt].y;
        float b0 = acc[nt][2] + bias2[nt].x;
        float b1 = acc[nt][3] + bias2[nt].y;
        vA[2*nt] = a0; vA[2*nt+1] = a1;
        vB[2*nt] = b0; vB[2*nt+1] = b1;
        s1A += a0 + a1; s2A += a0*a0 + a1*a1;
        s1B += b0 + b1; s2B += b0*b0 + b1*b1;
    }
#pragma unroll
    for (int m = 1; m <= 2; m <<= 1) {
        s1A += __shfl_xor_sync(0xffffffffu, s1A, m);
        s2A += __shfl_xor_sync(0xffffffffu, s2A, m);
        s1B += __shfl_xor_sync(0xffffffffu, s1B, m);
        s2B += __shfl_xor_sync(0xffffffffu, s2B, m);
    }
    const float muA = s1A * (1.0f/64.0f);
    const float muB = s1B * (1.0f/64.0f);
    const float rsA = rsqrtf(s2A * (1.0f/64.0f) - muA*muA + 1e-5f);
    const float rsB = rsqrtf(s2B * (1.0f/64.0f) - muB*muB + 1e-5f);

    // ---- LN affine + row max ----
    float mxA = -3.4e38f, mxB = -3.4e38f;
#pragma unroll
    for (int nt = 0; nt < 8; ++nt) {
        float zA0 = (vA[2*nt]   - muA) * rsA * gam2[nt].x + bet2[nt].x;
        float zA1 = (vA[2*nt+1] - muA) * rsA * gam2[nt].y + bet2[nt].y;
        float zB0 = (vB[2*nt]   - muB) * rsB * gam2[nt].x + bet2[nt].x;
        float zB1 = (vB[2*nt+1] - muB) * rsB * gam2[nt].y + bet2[nt].y;
        vA[2*nt] = zA0; vA[2*nt+1] = zA1;
        vB[2*nt] = zB0; vB[2*nt+1] = zB1;
        mxA = fmaxf(mxA, fmaxf(zA0, zA1));
        mxB = fmaxf(mxB, fmaxf(zB0, zB1));
    }
#pragma unroll
    for (int m = 1; m <= 2; m <<= 1) {
        mxA = fmaxf(mxA, __shfl_xor_sync(0xffffffffu, mxA, m));
        mxB = fmaxf(mxB, __shfl_xor_sync(0xffffffffu, mxB, m));
    }

    // ---- exp + row sum ----
    float sA = 0.f, sB = 0.f;
#pragma unroll
    for (int i = 0; i < 16; ++i) {
        float eA = __expf(vA[i] - mxA);
        float eB = __expf(vB[i] - mxB);
        vA[i] = eA; vB[i] = eB;
        sA += eA; sB += eB;
    }
#pragma unroll
    for (int m = 1; m <= 2; m <<= 1) {
        sA += __shfl_xor_sync(0xffffffffu, sA, m);
        sB += __shfl_xor_sync(0xffffffffu, sB, m);
    }
    const float invA = __fdividef(1.0f, sA);
    const float invB = __fdividef(1.0f, sB);

    // ---- normalize, cost dot, transport partials ----
    float costp = 0.f;
    float t[16];
#pragma unroll
    for (int nt = 0; nt < 8; ++nt) {
        float pA0 = vA[2*nt]   * invA, pA1 = vA[2*nt+1] * invA;
        float pB0 = vB[2*nt]   * invB, pB1 = vB[2*nt+1] * invB;
        costp += pA0 * ms2[nt].x + pA1 * ms2[nt].y
               + pB0 * ms2[nt].x + pB1 * ms2[nt].y;
        t[2*nt]   = xfA * pA0 + xfB * pB0;
        t[2*nt+1] = xfA * pA1 + xfB * pB1;
    }

    // ---- transport: reduce across the 8 quads (rows of this warp) ----
#pragma unroll
    for (int m = 4; m <= 16; m <<= 1)
#pragma unroll
        for (int i = 0; i < 16; ++i)
            t[i] += __shfl_xor_sync(0xffffffffu, t[i], m);
    if (q == 0) {
#pragma unroll
        for (int nt = 0; nt < 8; ++nt)
            *(float2*)&txbuf[wid][8*nt + c2] = make_float2(t[2*nt], t[2*nt+1]);
    }

    // ---- cost warp reduce ----
#pragma unroll
    for (int m = 1; m <= 16; m <<= 1)
        costp += __shfl_xor_sync(0xffffffffu, costp, m);
    if (lane == 0) cred[wid] = costp;
    __syncthreads();

    // ---- combine warps: output row + cost atomic ----
    if (tid < FEA)
        out[xob + tid] = (txbuf[0][tid] + txbuf[1][tid])
                       + (txbuf[2][tid] + txbuf[3][tid]);
    if (tid == 0 && out_size > COST_IDX)
        atomicAdd(&out[COST_IDX], (cred[0] + cred[1] + cred[2] + cred[3]) * INV_CNT);
}

extern "C" void kernel_launch(void* const* d_in, const int* in_sizes, int n_in,
                              void* d_out, int out_size) {
    const float* x     = (const float*)d_in[0];
    const float* P     = (const float*)d_in[1];
    const float* mask  = (const float*)d_in[2];
    const float* W     = (const float*)d_in[3];
    const float* bias  = (const float*)d_in[4];
    const float* gamma = (const float*)d_in[5];
    const float* beta  = (const float*)d_in[6];
    float* out = (float*)d_out;

    ot_prep_kernel<<<8, 256>>>(W, out, out_size);
    ot_mma_kernel<<<NTOT, 128>>>(x, P, mask, bias, gamma, beta, out, out_size);
}

// round 7
// speedup vs baseline: 1.8135x; 1.0635x over previous
#include <cuda_runtime.h>
#include <cstdint>

// ---------------- problem constants ----------------
#define FEA      64
#define NTOT     14112
#define COST_IDX (NTOT * FEA)               /* 903168 */
#define INV_CNT  (1.0f / (14112.0f * 4096.0f))

// W b-fragments, hi/lo bf16x2.
// Flat u32 index t = ((i*4 + ks)*32 + lane)*4 + w  (i,ks<4, lane<32, w<4):
// the 4 uint4 loads per (ks,lane) are lane-consecutive -> coalesced.
// Word (i,w): idx16 = i*4+w = nt*2+r. K-PERMUTED to match float4 A loads:
//   k_orig = 16*ks + 4*(lane&3) + 2*r + {0,1}
__device__ unsigned g_Bfh[2048];
__device__ unsigned g_Bfl[2048];

// ---------------- helpers ----------------
// split (x,y) into packed bf16x2 hi (lo16=x) + bf16x2 lo residual
__device__ __forceinline__ void cvtpair(float x, float y, uint32_t& h, uint32_t& l) {
    asm("cvt.rn.bf16x2.f32 %0, %1, %2;" : "=r"(h) : "f"(y), "f"(x));
    float hx = __uint_as_float(h << 16);
    float hy = __uint_as_float(h & 0xffff0000u);
    float lx = x - hx, ly = y - hy;
    asm("cvt.rn.bf16x2.f32 %0, %1, %2;" : "=r"(l) : "f"(ly), "f"(lx));
}

#define MMA_BF16(d, a, b) \
    asm volatile("mma.sync.aligned.m16n8k16.row.col.f32.bf16.bf16.f32 " \
                 "{%0,%1,%2,%3},{%4,%5,%6,%7},{%8,%9},{%0,%1,%2,%3};" \
                 : "+f"((d)[0]), "+f"((d)[1]), "+f"((d)[2]), "+f"((d)[3]) \
                 : "r"((a)[0]), "r"((a)[1]), "r"((a)[2]), "r"((a)[3]), \
                   "r"((b)[0]), "r"((b)[1]))

// ---------------- prep: W -> b-fragment tables (permuted k) ----------------
__global__ void ot_prep_kernel(const float* __restrict__ W,
                               float* __restrict__ out, int out_size) {
    int t = blockIdx.x * blockDim.x + threadIdx.x;   // 0..2047
    if (t < 2048) {
        int w    = t & 3;
        int lane = (t >> 2) & 31;
        int ks   = (t >> 7) & 3;
        int i    = t >> 9;
        int idx16 = i * 4 + w;        // nt*2 + r
        int nt   = idx16 >> 1;
        int r    = idx16 & 1;
        int nn   = (lane >> 2) + 8 * nt;                       // B col (output h)
        int k    = 16 * ks + ((lane & 3) << 2) + (r << 1);     // permuted k
        uint32_t h, l;
        cvtpair(W[nn * 64 + k], W[nn * 64 + k + 1], h, l);
        g_Bfh[t] = h;
        g_Bfl[t] = l;
    }
    if (t == 0)
        for (int i = COST_IDX; i < out_size; ++i) out[i] = 0.0f;
}

// ---------------- main kernel: 1 CTA / problem, register-resident ----------
__global__ void __launch_bounds__(128)
ot_mma_kernel(const float* __restrict__ x, const float* __restrict__ P,
              const float* __restrict__ mask, const float* __restrict__ bias,
              const float* __restrict__ gamma, const float* __restrict__ beta,
              float* __restrict__ out, int out_size) {

    __shared__ float txbuf[4][64];
    __shared__ float cred[4];

    const int n    = blockIdx.x;
    const int tid  = threadIdx.x;
    const int lane = tid & 31;
    const int wid  = tid >> 5;
    const int q    = lane >> 2;          // group id 0..7
    const int tg   = lane & 3;           // thread-in-group
    const int c2   = tg << 1;            // col pair base

    // n -> (b, v, p); x/out row base
    const int bb = n / (21 * 42);
    const int rm = n - bb * (21 * 42);
    const int vv = rm / 42;
    const int pp = rm - vv * 42;
    const size_t xob = ((size_t)(bb * 42 + pp) * 21 + vv) * FEA;

    const int fA = 16 * wid + q;         // this thread's two M rows
    const int fB = fA + 8;

    // ---- hoisted DRAM-latency loads: x row values + mask row ----
    const float xfA = x[xob + fA];
    const float xfB = x[xob + fB];
    float2 ms2[8];
    {
        const float2* m2 = (const float2*)(mask + (size_t)n * FEA);
#pragma unroll
        for (int nt = 0; nt < 8; ++nt) ms2[nt] = m2[4 * nt + tg];
    }

    // ---- A fragments: one float4 per row per 16-k chunk (permuted k) ----
    const float4* P4 = (const float4*)(P + ((size_t)n << 12));
    uint32_t ahA[4][2], alA[4][2], ahB[4][2], alB[4][2];   // [chunk][lo/hi word]
    {
        const int baseA = fA * 16 + tg;
        const int baseB = fB * 16 + tg;
#pragma unroll
        for (int j = 0; j < 4; ++j) {
            float4 ua = P4[baseA + 4 * j];
            float4 ub = P4[baseB + 4 * j];
            cvtpair(ua.x, ua.y, ahA[j][0], alA[j][0]);
            cvtpair(ua.z, ua.w, ahA[j][1], alA[j][1]);
            cvtpair(ub.x, ub.y, ahB[j][0], alB[j][0]);
            cvtpair(ub.z, ub.w, ahB[j][1], alB[j][1]);
        }
    }

    // ---- GEMM: 96 HMMA, B streamed per k-step (coalesced table) ----
    float acc[8][4];
#pragma unroll
    for (int nt = 0; nt < 8; ++nt)
#pragma unroll
        for (int j = 0; j < 4; ++j) acc[nt][j] = 0.f;

#pragma unroll
    for (int ks = 0; ks < 4; ++ks) {
        uint4 bh4[4], bl4[4];
#pragma unroll
        for (int i = 0; i < 4; ++i) {
            int u4idx = (i * 4 + ks) * 32 + lane;      // lane-consecutive
            bh4[i] = ((const uint4*)g_Bfh)[u4idx];
            bl4[i] = ((const uint4*)g_Bfl)[u4idx];
        }
        const uint32_t* bhw = (const uint32_t*)bh4;
        const uint32_t* blw = (const uint32_t*)bl4;

        uint32_t ah[4] = { ahA[ks][0], ahB[ks][0], ahA[ks][1], ahB[ks][1] };
        uint32_t al[4] = { alA[ks][0], alB[ks][0], alA[ks][1], alB[ks][1] };

#pragma unroll
        for (int nt = 0; nt < 8; ++nt) {
            uint32_t bfh[2] = { bhw[2*nt], bhw[2*nt+1] };
            uint32_t bfl[2] = { blw[2*nt], blw[2*nt+1] };
            MMA_BF16(acc[nt], ah, bfh);   // Phi * Whi
            MMA_BF16(acc[nt], al, bfh);   // Plo * Whi
            MMA_BF16(acc[nt], ah, bfl);   // Phi * Wlo
        }
    }

    // ---- per-column params (L1/L2-hot, short latency) ----
    float2 bias2[8], gam2[8], bet2[8];
    {
        const float2* b2 = (const float2*)bias;
        const float2* g2 = (const float2*)gamma;
        const float2* e2 = (const float2*)beta;
#pragma unroll
        for (int nt = 0; nt < 8; ++nt) {
            int ix = 4 * nt + tg;
            bias2[nt] = b2[ix]; gam2[nt] = g2[ix]; bet2[nt] = e2[ix];
        }
    }

    // ---- bias + LN stats (rows fA, fB live in this quad) ----
    float vA[16], vB[16];
    float s1A = 0.f, s2A = 0.f, s1B = 0.f, s2B = 0.f;
#pragma unroll
    for (int nt = 0; nt < 8; ++nt) {
        float a0 = acc[nt][0] + bias2[nt].x;
        float a1 = acc[nt][1] + bias2[nt].y;
        float b0 = acc[nt][2] + bias2[nt].x;
        float b1 = acc[nt][3] + bias2[nt].y;
        vA[2*nt] = a0; vA[2*nt+1] = a1;
        vB[2*nt] = b0; vB[2*nt+1] = b1;
        s1A += a0 + a1; s2A += a0*a0 + a1*a1;
        s1B += b0 + b1; s2B += b0*b0 + b1*b1;
    }
#pragma unroll
    for (int m = 1; m <= 2; m <<= 1) {
        s1A += __shfl_xor_sync(0xffffffffu, s1A, m);
        s2A += __shfl_xor_sync(0xffffffffu, s2A, m);
        s1B += __shfl_xor_sync(0xffffffffu, s1B, m);
        s2B += __shfl_xor_sync(0xffffffffu, s2B, m);
    }
    const float muA = s1A * (1.0f/64.0f);
    const float muB = s1B * (1.0f/64.0f);
    const float rsA = rsqrtf(s2A * (1.0f/64.0f) - muA*muA + 1e-5f);
    const float rsB = rsqrtf(s2B * (1.0f/64.0f) - muB*muB + 1e-5f);

    // ---- LN affine + row max ----
    float mxA = -3.4e38f, mxB = -3.4e38f;
#pragma unroll
    for (int nt = 0; nt < 8; ++nt) {
        float zA0 = (vA[2*nt]   - muA) * rsA * gam2[nt].x + bet2[nt].x;
        float zA1 = (vA[2*nt+1] - muA) * rsA * gam2[nt].y + bet2[nt].y;
        float zB0 = (vB[2*nt]   - muB) * rsB * gam2[nt].x + bet2[nt].x;
        float zB1 = (vB[2*nt+1] - muB) * rsB * gam2[nt].y + bet2[nt].y;
        vA[2*nt] = zA0; vA[2*nt+1] = zA1;
        vB[2*nt] = zB0; vB[2*nt+1] = zB1;
        mxA = fmaxf(mxA, fmaxf(zA0, zA1));
        mxB = fmaxf(mxB, fmaxf(zB0, zB1));
    }
#pragma unroll
    for (int m = 1; m <= 2; m <<= 1) {
        mxA = fmaxf(mxA, __shfl_xor_sync(0xffffffffu, mxA, m));
        mxB = fmaxf(mxB, __shfl_xor_sync(0xffffffffu, mxB, m));
    }

    // ---- exp + row sum ----
    float sA = 0.f, sB = 0.f;
#pragma unroll
    for (int i = 0; i < 16; ++i) {
        float eA = __expf(vA[i] - mxA);
        float eB = __expf(vB[i] - mxB);
        vA[i] = eA; vB[i] = eB;
        sA += eA; sB += eB;
    }
#pragma unroll
    for (int m = 1; m <= 2; m <<= 1) {
        sA += __shfl_xor_sync(0xffffffffu, sA, m);
        sB += __shfl_xor_sync(0xffffffffu, sB, m);
    }
    const float invA = __fdividef(1.0f, sA);
    const float invB = __fdividef(1.0f, sB);

    // ---- normalize, cost dot, transport partials ----
    float costp = 0.f;
    float t[16];
#pragma unroll
    for (int nt = 0; nt < 8; ++nt) {
        float pA0 = vA[2*nt]   * invA, pA1 = vA[2*nt+1] * invA;
        float pB0 = vB[2*nt]   * invB, pB1 = vB[2*nt+1] * invB;
        costp += pA0 * ms2[nt].x + pA1 * ms2[nt].y
               + pB0 * ms2[nt].x + pB1 * ms2[nt].y;
        t[2*nt]   = xfA * pA0 + xfB * pB0;
        t[2*nt+1] = xfA * pA1 + xfB * pB1;
    }

    // ---- transport: reduce-scatter over the 8 quads (14 shuffles) ----
    // final owner: thread (q,tg) holds cols 8q+2tg, 8q+2tg+1
    {
        const bool hi4 = (q & 4) != 0;
        float u[8];
#pragma unroll
        for (int j = 0; j < 8; ++j) {
            float send = hi4 ? t[j] : t[8 + j];
            float recv = __shfl_xor_sync(0xffffffffu, send, 16);
            u[j] = (hi4 ? t[8 + j] : t[j]) + recv;
        }
        const bool hi2 = (q & 2) != 0;
        float v[4];
#pragma unroll
        for (int j = 0; j < 4; ++j) {
            float send = hi2 ? u[j] : u[4 + j];
            float recv = __shfl_xor_sync(0xffffffffu, send, 8);
            v[j] = (hi2 ? u[4 + j] : u[j]) + recv;
        }
        const bool hi1 = (q & 1) != 0;
        float s0 = hi1 ? v[0] : v[2];
        float r0 = __shfl_xor_sync(0xffffffffu, s0, 4);
        float w0 = (hi1 ? v[2] : v[0]) + r0;
        float s1 = hi1 ? v[1] : v[3];
        float r1 = __shfl_xor_sync(0xffffffffu, s1, 4);
        float w1 = (hi1 ? v[3] : v[1]) + r1;
        *(float2*)&txbuf[wid][8 * q + c2] = make_float2(w0, w1);
    }

    // ---- cost warp reduce ----
#pragma unroll
    for (int m = 1; m <= 16; m <<= 1)
        costp += __shfl_xor_sync(0xffffffffu, costp, m);
    if (lane == 0) cred[wid] = costp;
    __syncthreads();

    // ---- combine warps: output row + cost atomic ----
    if (tid < FEA)
        out[xob + tid] = (txbuf[0][tid] + txbuf[1][tid])
                       + (txbuf[2][tid] + txbuf[3][tid]);
    if (tid == 0 && out_size > COST_IDX)
        atomicAdd(&out[COST_IDX], (cred[0] + cred[1] + cred[2] + cred[3]) * INV_CNT);
}

extern "C" void kernel_launch(void* const* d_in, const int* in_sizes, int n_in,
                              void* d_out, int out_size) {
    const float* x     = (const float*)d_in[0];
    const float* P     = (const float*)d_in[1];
    const float* mask  = (const float*)d_in[2];
    const float* W     = (const float*)d_in[3];
    const float* bias  = (const float*)d_in[4];
    const float* gamma = (const float*)d_in[5];
    const float* beta  = (const float*)d_in[6];
    float* out = (float*)d_out;

    ot_prep_kernel<<<8, 256>>>(W, out, out_size);
    ot_mma_kernel<<<NTOT, 128>>>(x, P, mask, bias, gamma, beta, out, out_size);
}

// round 8
// speedup vs baseline: 2.0781x; 1.1459x over previous
#include <cuda_runtime.h>
#include <cuda_fp16.h>
#include <cstdint>

// ---------------- problem constants ----------------
#define FEA      64
#define NTOT     14112
#define COST_IDX (NTOT * FEA)               /* 903168 */
#define INV_CNT  (1.0f / (14112.0f * 4096.0f))

// W b-fragments, fp16x2 (hi only — 2-term split).
// Flat u32 index t = ((i*4 + ks)*32 + lane)*4 + w  (i,ks<4, lane<32, w<4):
// the 4 uint4 loads per (ks,lane) are lane-consecutive -> coalesced.
// Word (i,w): idx16 = i*4+w = nt*2+r. K-PERMUTED to match float4 A loads:
//   k_orig = 16*ks + 4*(lane&3) + 2*r + {0,1}
__device__ unsigned g_Bfh[2048];

// ---------------- helpers ----------------
// split (x,y) into packed fp16x2 hi (lo16=x) + fp16x2 lo residual
__device__ __forceinline__ void cvtpair(float x, float y, uint32_t& h, uint32_t& l) {
    __half2 hh = __floats2half2_rn(x, y);
    h = *(uint32_t*)&hh;
    float2 hf = __half22float2(hh);
    __half2 ll = __floats2half2_rn(x - hf.x, y - hf.y);
    l = *(uint32_t*)&ll;
}

#define MMA_F16(d, a, b) \
    asm volatile("mma.sync.aligned.m16n8k16.row.col.f32.f16.f16.f32 " \
                 "{%0,%1,%2,%3},{%4,%5,%6,%7},{%8,%9},{%0,%1,%2,%3};" \
                 : "+f"((d)[0]), "+f"((d)[1]), "+f"((d)[2]), "+f"((d)[3]) \
                 : "r"((a)[0]), "r"((a)[1]), "r"((a)[2]), "r"((a)[3]), \
                   "r"((b)[0]), "r"((b)[1]))

// ---------------- prep: W -> fp16 b-fragment table (permuted k) ------------
__global__ void ot_prep_kernel(const float* __restrict__ W,
                               float* __restrict__ out, int out_size) {
    int t = blockIdx.x * blockDim.x + threadIdx.x;   // 0..2047
    if (t < 2048) {
        int w    = t & 3;
        int lane = (t >> 2) & 31;
        int ks   = (t >> 7) & 3;
        int i    = t >> 9;
        int idx16 = i * 4 + w;        // nt*2 + r
        int nt   = idx16 >> 1;
        int r    = idx16 & 1;
        int nn   = (lane >> 2) + 8 * nt;                       // B col (output h)
        int k    = 16 * ks + ((lane & 3) << 2) + (r << 1);     // permuted k
        __half2 hh = __floats2half2_rn(W[nn * 64 + k], W[nn * 64 + k + 1]);
        g_Bfh[t] = *(uint32_t*)&hh;
    }
    if (t == 0)
        for (int i = COST_IDX; i < out_size; ++i) out[i] = 0.0f;
}

// ---------------- main kernel: 1 CTA / problem, register-resident ----------
__global__ void __launch_bounds__(128)
ot_mma_kernel(const float* __restrict__ x, const float* __restrict__ P,
              const float* __restrict__ mask, const float* __restrict__ bias,
              const float* __restrict__ gamma, const float* __restrict__ beta,
              float* __restrict__ out, int out_size) {

    __shared__ float txbuf[4][64];
    __shared__ float cred[4];

    const int n    = blockIdx.x;
    const int tid  = threadIdx.x;
    const int lane = tid & 31;
    const int wid  = tid >> 5;
    const int q    = lane >> 2;          // group id 0..7
    const int tg   = lane & 3;           // thread-in-group
    const int c2   = tg << 1;            // col pair base

    // n -> (b, v, p); x/out row base
    const int bb = n / (21 * 42);
    const int rm = n - bb * (21 * 42);
    const int vv = rm / 42;
    const int pp = rm - vv * 42;
    const size_t xob = ((size_t)(bb * 42 + pp) * 21 + vv) * FEA;

    const int fA = 16 * wid + q;         // this thread's two M rows
    const int fB = fA + 8;

    // ---- hoisted DRAM-latency loads: x row values + mask row ----
    const float xfA = x[xob + fA];
    const float xfB = x[xob + fB];
    float2 ms2[8];
    {
        const float2* m2 = (const float2*)(mask + (size_t)n * FEA);
#pragma unroll
        for (int nt = 0; nt < 8; ++nt) ms2[nt] = m2[4 * nt + tg];
    }

    // ---- A fragments: one float4 per row per 16-k chunk (permuted k) ----
    const float4* P4 = (const float4*)(P + ((size_t)n << 12));
    uint32_t ahA[4][2], alA[4][2], ahB[4][2], alB[4][2];   // [chunk][lo/hi word]
    {
        const int baseA = fA * 16 + tg;
        const int baseB = fB * 16 + tg;
#pragma unroll
        for (int j = 0; j < 4; ++j) {
            float4 ua = P4[baseA + 4 * j];
            float4 ub = P4[baseB + 4 * j];
            cvtpair(ua.x, ua.y, ahA[j][0], alA[j][0]);
            cvtpair(ua.z, ua.w, ahA[j][1], alA[j][1]);
            cvtpair(ub.x, ub.y, ahB[j][0], alB[j][0]);
            cvtpair(ub.z, ub.w, ahB[j][1], alB[j][1]);
        }
    }

    // ---- GEMM: 64 HMMA (2-term fp16 split), B streamed per k-step ----
    float acc[8][4];
#pragma unroll
    for (int nt = 0; nt < 8; ++nt)
#pragma unroll
        for (int j = 0; j < 4; ++j) acc[nt][j] = 0.f;

#pragma unroll
    for (int ks = 0; ks < 4; ++ks) {
        uint4 bh4[4];
#pragma unroll
        for (int i = 0; i < 4; ++i) {
            int u4idx = (i * 4 + ks) * 32 + lane;      // lane-consecutive
            bh4[i] = ((const uint4*)g_Bfh)[u4idx];
        }
        const uint32_t* bhw = (const uint32_t*)bh4;

        uint32_t ah[4] = { ahA[ks][0], ahB[ks][0], ahA[ks][1], ahB[ks][1] };
        uint32_t al[4] = { alA[ks][0], alB[ks][0], alA[ks][1], alB[ks][1] };

#pragma unroll
        for (int nt = 0; nt < 8; ++nt) {
            uint32_t bfh[2] = { bhw[2*nt], bhw[2*nt+1] };
            MMA_F16(acc[nt], ah, bfh);   // Phi * Whi
            MMA_F16(acc[nt], al, bfh);   // Plo * Whi
        }
    }

    // ---- per-column params (L1/L2-hot, short latency) ----
    float2 bias2[8], gam2[8], bet2[8];
    {
        const float2* b2 = (const float2*)bias;
        const float2* g2 = (const float2*)gamma;
        const float2* e2 = (const float2*)beta;
#pragma unroll
        for (int nt = 0; nt < 8; ++nt) {
            int ix = 4 * nt + tg;
            bias2[nt] = b2[ix]; gam2[nt] = g2[ix]; bet2[nt] = e2[ix];
        }
    }

    // ---- bias + LN stats (rows fA, fB live in this quad) ----
    float vA[16], vB[16];
    float s1A = 0.f, s2A = 0.f, s1B = 0.f, s2B = 0.f;
#pragma unroll
    for (int nt = 0; nt < 8; ++nt) {
        float a0 = acc[nt][0] + bias2[nt].x;
        float a1 = acc[nt][1] + bias2[nt].y;
        float b0 = acc[nt][2] + bias2[nt].x;
        float b1 = acc[nt][3] + bias2[nt].y;
        vA[2*nt] = a0; vA[2*nt+1] = a1;
        vB[2*nt] = b0; vB[2*nt+1] = b1;
        s1A += a0 + a1; s2A += a0*a0 + a1*a1;
        s1B += b0 + b1; s2B += b0*b0 + b1*b1;
    }
#pragma unroll
    for (int m = 1; m <= 2; m <<= 1) {
        s1A += __shfl_xor_sync(0xffffffffu, s1A, m);
        s2A += __shfl_xor_sync(0xffffffffu, s2A, m);
        s1B += __shfl_xor_sync(0xffffffffu, s1B, m);
        s2B += __shfl_xor_sync(0xffffffffu, s2B, m);
    }
    const float muA = s1A * (1.0f/64.0f);
    const float muB = s1B * (1.0f/64.0f);
    const float rsA = rsqrtf(s2A * (1.0f/64.0f) - muA*muA + 1e-5f);
    const float rsB = rsqrtf(s2B * (1.0f/64.0f) - muB*muB + 1e-5f);

    // ---- LN affine + row max ----
    float mxA = -3.4e38f, mxB = -3.4e38f;
#pragma unroll
    for (int nt = 0; nt < 8; ++nt) {
        float zA0 = (vA[2*nt]   - muA) * rsA * gam2[nt].x + bet2[nt].x;
        float zA1 = (vA[2*nt+1] - muA) * rsA * gam2[nt].y + bet2[nt].y;
        float zB0 = (vB[2*nt]   - muB) * rsB * gam2[nt].x + bet2[nt].x;
        float zB1 = (vB[2*nt+1] - muB) * rsB * gam2[nt].y + bet2[nt].y;
        vA[2*nt] = zA0; vA[2*nt+1] = zA1;
        vB[2*nt] = zB0; vB[2*nt+1] = zB1;
        mxA = fmaxf(mxA, fmaxf(zA0, zA1));
        mxB = fmaxf(mxB, fmaxf(zB0, zB1));
    }
#pragma unroll
    for (int m = 1; m <= 2; m <<= 1) {
        mxA = fmaxf(mxA, __shfl_xor_sync(0xffffffffu, mxA, m));
        mxB = fmaxf(mxB, __shfl_xor_sync(0xffffffffu, mxB, m));
    }

    // ---- exp + row sum ----
    float sA = 0.f, sB = 0.f;
#pragma unroll
    for (int i = 0; i < 16; ++i) {
        float eA = __expf(vA[i] - mxA);
        float eB = __expf(vB[i] - mxB);
        vA[i] = eA; vB[i] = eB;
        sA += eA; sB += eB;
    }
#pragma unroll
    for (int m = 1; m <= 2; m <<= 1) {
        sA += __shfl_xor_sync(0xffffffffu, sA, m);
        sB += __shfl_xor_sync(0xffffffffu, sB, m);
    }
    const float invA = __fdividef(1.0f, sA);
    const float invB = __fdividef(1.0f, sB);

    // ---- normalize, cost dot, transport partials ----
    float costp = 0.f;
    float t[16];
#pragma unroll
    for (int nt = 0; nt < 8; ++nt) {
        float pA0 = vA[2*nt]   * invA, pA1 = vA[2*nt+1] * invA;
        float pB0 = vB[2*nt]   * invB, pB1 = vB[2*nt+1] * invB;
        costp += pA0 * ms2[nt].x + pA1 * ms2[nt].y
               + pB0 * ms2[nt].x + pB1 * ms2[nt].y;
        t[2*nt]   = xfA * pA0 + xfB * pB0;
        t[2*nt+1] = xfA * pA1 + xfB * pB1;
    }

    // ---- transport: reduce-scatter over the 8 quads (14 shuffles) ----
    // final owner: thread (q,tg) holds cols 8q+2tg, 8q+2tg+1
    {
        const bool hi4 = (q & 4) != 0;
        float u[8];
#pragma unroll
        for (int j = 0; j < 8; ++j) {
            float send = hi4 ? t[j] : t[8 + j];
            float recv = __shfl_xor_sync(0xffffffffu, send, 16);
            u[j] = (hi4 ? t[8 + j] : t[j]) + recv;
        }
        const bool hi2 = (q & 2) != 0;
        float v[4];
#pragma unroll
        for (int j = 0; j < 4; ++j) {
            float send = hi2 ? u[j] : u[4 + j];
            float recv = __shfl_xor_sync(0xffffffffu, send, 8);
            v[j] = (hi2 ? u[4 + j] : u[j]) + recv;
        }
        const bool hi1 = (q & 1) != 0;
        float s0 = hi1 ? v[0] : v[2];
        float r0 = __shfl_xor_sync(0xffffffffu, s0, 4);
        float w0 = (hi1 ? v[2] : v[0]) + r0;
        float s1 = hi1 ? v[1] : v[3];
        float r1 = __shfl_xor_sync(0xffffffffu, s1, 4);
        float w1 = (hi1 ? v[3] : v[1]) + r1;
        *(float2*)&txbuf[wid][8 * q + c2] = make_float2(w0, w1);
    }

    // ---- cost warp reduce ----
#pragma unroll
    for (int m = 1; m <= 16; m <<= 1)
        costp += __shfl_xor_sync(0xffffffffu, costp, m);
    if (lane == 0) cred[wid] = costp;
    __syncthreads();

    // ---- combine warps: output row + cost atomic ----
    if (tid < FEA)
        out[xob + tid] = (txbuf[0][tid] + txbuf[1][tid])
                       + (txbuf[2][tid] + txbuf[3][tid]);
    if (tid == 0 && out_size > COST_IDX)
        atomicAdd(&out[COST_IDX], (cred[0] + cred[1] + cred[2] + cred[3]) * INV_CNT);
}

extern "C" void kernel_launch(void* const* d_in, const int* in_sizes, int n_in,
                              void* d_out, int out_size) {
    const float* x     = (const float*)d_in[0];
    const float* P     = (const float*)d_in[1];
    const float* mask  = (const float*)d_in[2];
    const float* W     = (const float*)d_in[3];
    const float* bias  = (const float*)d_in[4];
    const float* gamma = (const float*)d_in[5];
    const float* beta  = (const float*)d_in[6];
    float* out = (float*)d_out;

    ot_prep_kernel<<<8, 256>>>(W, out, out_size);
    ot_mma_kernel<<<NTOT, 128>>>(x, P, mask, bias, gamma, beta, out, out_size);
}

// round 9
// speedup vs baseline: 2.1996x; 1.0585x over previous
#include <cuda_runtime.h>
#include <cuda_fp16.h>
#include <cstdint>

// ---------------- problem constants ----------------
#define FEA      64
#define NTOT     14112
#define COST_IDX (NTOT * FEA)               /* 903168 */
#define INV_CNT  (1.0f / (14112.0f * 4096.0f))
#define LOG2E    1.4426950408889634f

// W b-fragments, fp16x2 (hi only — 2-term split).
// Flat u32 index t = ((i*4 + ks)*32 + lane)*4 + w  (i,ks<4, lane<32, w<4):
// the 4 uint4 loads per (ks,lane) are lane-consecutive -> coalesced.
// Word (i,w): idx16 = i*4+w = nt*2+r. K-PERMUTED to match float4 A loads:
//   k_orig = 16*ks + 4*(lane&3) + 2*r + {0,1}
__device__ unsigned g_Bfh[2048];

// ---------------- helpers ----------------
// split (x,y) into packed fp16x2 hi (lo16=x) + fp16x2 lo residual
__device__ __forceinline__ void cvtpair(float x, float y, uint32_t& h, uint32_t& l) {
    __half2 hh = __floats2half2_rn(x, y);
    h = *(uint32_t*)&hh;
    float2 hf = __half22float2(hh);
    __half2 ll = __floats2half2_rn(x - hf.x, y - hf.y);
    l = *(uint32_t*)&ll;
}

__device__ __forceinline__ float ex2f(float a) {
    float r;
    asm("ex2.approx.f32 %0, %1;" : "=f"(r) : "f"(a));
    return r;
}

#define MMA_F16(d, a, b) \
    asm volatile("mma.sync.aligned.m16n8k16.row.col.f32.f16.f16.f32 " \
                 "{%0,%1,%2,%3},{%4,%5,%6,%7},{%8,%9},{%0,%1,%2,%3};" \
                 : "+f"((d)[0]), "+f"((d)[1]), "+f"((d)[2]), "+f"((d)[3]) \
                 : "r"((a)[0]), "r"((a)[1]), "r"((a)[2]), "r"((a)[3]), \
                   "r"((b)[0]), "r"((b)[1]))

// ---------------- prep: W -> fp16 b-fragment table (permuted k) ------------
__global__ void ot_prep_kernel(const float* __restrict__ W,
                               float* __restrict__ out, int out_size) {
    int t = blockIdx.x * blockDim.x + threadIdx.x;   // 0..2047
    if (t < 2048) {
        int w    = t & 3;
        int lane = (t >> 2) & 31;
        int ks   = (t >> 7) & 3;
        int i    = t >> 9;
        int idx16 = i * 4 + w;        // nt*2 + r
        int nt   = idx16 >> 1;
        int r    = idx16 & 1;
        int nn   = (lane >> 2) + 8 * nt;                       // B col (output h)
        int k    = 16 * ks + ((lane & 3) << 2) + (r << 1);     // permuted k
        __half2 hh = __floats2half2_rn(W[nn * 64 + k], W[nn * 64 + k + 1]);
        g_Bfh[t] = *(uint32_t*)&hh;
    }
    if (t == 0)
        for (int i = COST_IDX; i < out_size; ++i) out[i] = 0.0f;
}

// ---------------- main kernel: 1 CTA / problem, register-resident ----------
__global__ void __launch_bounds__(128, 8)
ot_mma_kernel(const float* __restrict__ x, const float* __restrict__ P,
              const float* __restrict__ mask, const float* __restrict__ bias,
              const float* __restrict__ gamma, const float* __restrict__ beta,
              float* __restrict__ out, int out_size) {

    __shared__ float txbuf[4][64];
    __shared__ float cred[4];

    const int n    = blockIdx.x;
    const int tid  = threadIdx.x;
    const int lane = tid & 31;
    const int wid  = tid >> 5;
    const int q    = lane >> 2;          // group id 0..7
    const int tg   = lane & 3;           // thread-in-group
    const int c2   = tg << 1;            // col pair base

    // n -> (b, v, p); x/out row base
    const int bb = n / (21 * 42);
    const int rm = n - bb * (21 * 42);
    const int vv = rm / 42;
    const int pp = rm - vv * 42;
    const size_t xob = ((size_t)(bb * 42 + pp) * 21 + vv) * FEA;

    const int fA = 16 * wid + q;         // this thread's two M rows
    const int fB = fA + 8;

    // ---- hoisted DRAM-latency loads: x row values + mask row ----
    const float xfA = x[xob + fA];
    const float xfB = x[xob + fB];
    float2 ms2[8];
    {
        const float2* m2 = (const float2*)(mask + (size_t)n * FEA);
#pragma unroll
        for (int nt = 0; nt < 8; ++nt) ms2[nt] = m2[4 * nt + tg];
    }

    // ---- A fragments: one float4 per row per 16-k chunk (permuted k) ----
    const float4* P4 = (const float4*)(P + ((size_t)n << 12));
    uint32_t ahA[4][2], alA[4][2], ahB[4][2], alB[4][2];   // [chunk][lo/hi word]
    {
        const int baseA = fA * 16 + tg;
        const int baseB = fB * 16 + tg;
#pragma unroll
        for (int j = 0; j < 4; ++j) {
            float4 ua = P4[baseA + 4 * j];
            float4 ub = P4[baseB + 4 * j];
            cvtpair(ua.x, ua.y, ahA[j][0], alA[j][0]);
            cvtpair(ua.z, ua.w, ahA[j][1], alA[j][1]);
            cvtpair(ub.x, ub.y, ahB[j][0], alB[j][0]);
            cvtpair(ub.z, ub.w, ahB[j][1], alB[j][1]);
        }
    }

    // ---- GEMM: 64 HMMA (2-term fp16 split), B streamed per k-step ----
    float acc[8][4];
#pragma unroll
    for (int nt = 0; nt < 8; ++nt)
#pragma unroll
        for (int j = 0; j < 4; ++j) acc[nt][j] = 0.f;

#pragma unroll
    for (int ks = 0; ks < 4; ++ks) {
        uint4 bh4[4];
#pragma unroll
        for (int i = 0; i < 4; ++i) {
            int u4idx = (i * 4 + ks) * 32 + lane;      // lane-consecutive
            bh4[i] = ((const uint4*)g_Bfh)[u4idx];
        }
        const uint32_t* bhw = (const uint32_t*)bh4;

        uint32_t ah[4] = { ahA[ks][0], ahB[ks][0], ahA[ks][1], ahB[ks][1] };
        uint32_t al[4] = { alA[ks][0], alB[ks][0], alA[ks][1], alB[ks][1] };

#pragma unroll
        for (int nt = 0; nt < 8; ++nt) {
            uint32_t bfh[2] = { bhw[2*nt], bhw[2*nt+1] };
            MMA_F16(acc[nt], ah, bfh);   // Phi * Whi
            MMA_F16(acc[nt], al, bfh);   // Plo * Whi
        }
    }

    // ---- per-column params (L1/L2-hot, short latency) ----
    float2 bias2[8], gam2[8], bet2[8];
    {
        const float2* b2 = (const float2*)bias;
        const float2* g2 = (const float2*)gamma;
        const float2* e2 = (const float2*)beta;
#pragma unroll
        for (int nt = 0; nt < 8; ++nt) {
            int ix = 4 * nt + tg;
            bias2[nt] = b2[ix]; gam2[nt] = g2[ix]; bet2[nt] = e2[ix];
        }
    }

    // ---- bias + LN stats (rows fA, fB live in this quad) ----
    float vA[16], vB[16];
    float s1A = 0.f, s2A = 0.f, s1B = 0.f, s2B = 0.f;
#pragma unroll
    for (int nt = 0; nt < 8; ++nt) {
        float a0 = acc[nt][0] + bias2[nt].x;
        float a1 = acc[nt][1] + bias2[nt].y;
        float b0 = acc[nt][2] + bias2[nt].x;
        float b1 = acc[nt][3] + bias2[nt].y;
        vA[2*nt] = a0; vA[2*nt+1] = a1;
        vB[2*nt] = b0; vB[2*nt+1] = b1;
        s1A += a0 + a1; s2A += a0*a0 + a1*a1;
        s1B += b0 + b1; s2B += b0*b0 + b1*b1;
    }
#pragma unroll
    for (int m = 1; m <= 2; m <<= 1) {
        s1A += __shfl_xor_sync(0xffffffffu, s1A, m);
        s2A += __shfl_xor_sync(0xffffffffu, s2A, m);
        s1B += __shfl_xor_sync(0xffffffffu, s1B, m);
        s2B += __shfl_xor_sync(0xffffffffu, s2B, m);
    }
    const float muA = s1A * (1.0f/64.0f);
    const float muB = s1B * (1.0f/64.0f);
    const float rsA = rsqrtf(s2A * (1.0f/64.0f) - muA*muA + 1e-5f);
    const float rsB = rsqrtf(s2B * (1.0f/64.0f) - muB*muB + 1e-5f);
    const float nmrA = -muA * rsA;       // z = (v*rsA + nmrA)*gamma + beta
    const float nmrB = -muB * rsB;

    // ---- LN affine (2 FFMA) + row max ----
    float mxA = -3.4e38f, mxB = -3.4e38f;
#pragma unroll
    for (int nt = 0; nt < 8; ++nt) {
        float tA0 = fmaf(vA[2*nt],   rsA, nmrA);
        float tA1 = fmaf(vA[2*nt+1], rsA, nmrA);
        float tB0 = fmaf(vB[2*nt],   rsB, nmrB);
        float tB1 = fmaf(vB[2*nt+1], rsB, nmrB);
        float zA0 = fmaf(tA0, gam2[nt].x, bet2[nt].x);
        float zA1 = fmaf(tA1, gam2[nt].y, bet2[nt].y);
        float zB0 = fmaf(tB0, gam2[nt].x, bet2[nt].x);
        float zB1 = fmaf(tB1, gam2[nt].y, bet2[nt].y);
        vA[2*nt] = zA0; vA[2*nt+1] = zA1;
        vB[2*nt] = zB0; vB[2*nt+1] = zB1;
        mxA = fmaxf(mxA, fmaxf(zA0, zA1));
        mxB = fmaxf(mxB, fmaxf(zB0, zB1));
    }
#pragma unroll
    for (int m = 1; m <= 2; m <<= 1) {
        mxA = fmaxf(mxA, __shfl_xor_sync(0xffffffffu, mxA, m));
        mxB = fmaxf(mxB, __shfl_xor_sync(0xffffffffu, mxB, m));
    }
    const float mxlA = mxA * LOG2E;
    const float mxlB = mxB * LOG2E;

    // ---- exp (FFMA + EX2) + row sum ----
    float sA = 0.f, sB = 0.f;
#pragma unroll
    for (int i = 0; i < 16; ++i) {
        float eA = ex2f(fmaf(vA[i], LOG2E, -mxlA));
        float eB = ex2f(fmaf(vB[i], LOG2E, -mxlB));
        vA[i] = eA; vB[i] = eB;
        sA += eA; sB += eB;
    }
#pragma unroll
    for (int m = 1; m <= 2; m <<= 1) {
        sA += __shfl_xor_sync(0xffffffffu, sA, m);
        sB += __shfl_xor_sync(0xffffffffu, sB, m);
    }
    const float invA = __fdividef(1.0f, sA);
    const float invB = __fdividef(1.0f, sB);
    const float sclA = xfA * invA;       // transport scale, normalization folded
    const float sclB = xfB * invB;

    // ---- cost dot (unnormalized) + transport partials ----
    float dotA = 0.f, dotB = 0.f;
    float t[16];
#pragma unroll
    for (int nt = 0; nt < 8; ++nt) {
        dotA = fmaf(vA[2*nt], ms2[nt].x, fmaf(vA[2*nt+1], ms2[nt].y, dotA));
        dotB = fmaf(vB[2*nt], ms2[nt].x, fmaf(vB[2*nt+1], ms2[nt].y, dotB));
        t[2*nt]   = fmaf(vA[2*nt],   sclA, vB[2*nt]   * sclB);
        t[2*nt+1] = fmaf(vA[2*nt+1], sclA, vB[2*nt+1] * sclB);
    }
    float costp = fmaf(dotA, invA, dotB * invB);

    // ---- transport: reduce-scatter over the 8 quads (14 shuffles) ----
    // final owner: thread (q,tg) holds cols 8q+2tg, 8q+2tg+1
    {
        const bool hi4 = (q & 4) != 0;
        float u[8];
#pragma unroll
        for (int j = 0; j < 8; ++j) {
            float send = hi4 ? t[j] : t[8 + j];
            float recv = __shfl_xor_sync(0xffffffffu, send, 16);
            u[j] = (hi4 ? t[8 + j] : t[j]) + recv;
        }
        const bool hi2 = (q & 2) != 0;
        float v[4];
#pragma unroll
        for (int j = 0; j < 4; ++j) {
            float send = hi2 ? u[j] : u[4 + j];
            float recv = __shfl_xor_sync(0xffffffffu, send, 8);
            v[j] = (hi2 ? u[4 + j] : u[j]) + recv;
        }
        const bool hi1 = (q & 1) != 0;
        float s0 = hi1 ? v[0] : v[2];
        float r0 = __shfl_xor_sync(0xffffffffu, s0, 4);
        float w0 = (hi1 ? v[2] : v[0]) + r0;
        float s1 = hi1 ? v[1] : v[3];
        float r1 = __shfl_xor_sync(0xffffffffu, s1, 4);
        float w1 = (hi1 ? v[3] : v[1]) + r1;
        *(float2*)&txbuf[wid][8 * q + c2] = make_float2(w0, w1);
    }

    // ---- cost warp reduce ----
#pragma unroll
    for (int m = 1; m <= 16; m <<= 1)
        costp += __shfl_xor_sync(0xffffffffu, costp, m);
    if (lane == 0) cred[wid] = costp;
    __syncthreads();

    // ---- combine warps: output row + cost atomic ----
    if (tid < FEA)
        out[xob + tid] = (txbuf[0][tid] + txbuf[1][tid])
                       + (txbuf[2][tid] + txbuf[3][tid]);
    if (tid == 0 && out_size > COST_IDX)
        atomicAdd(&out[COST_IDX], (cred[0] + cred[1] + cred[2] + cred[3]) * INV_CNT);
}

extern "C" void kernel_launch(void* const* d_in, const int* in_sizes, int n_in,
                              void* d_out, int out_size) {
    const float* x     = (const float*)d_in[0];
    const float* P     = (const float*)d_in[1];
    const float* mask  = (const float*)d_in[2];
    const float* W     = (const float*)d_in[3];
    const float* bias  = (const float*)d_in[4];
    const float* gamma = (const float*)d_in[5];
    const float* beta  = (const float*)d_in[6];
    float* out = (float*)d_out;

    ot_prep_kernel<<<8, 256>>>(W, out, out_size);
    ot_mma_kernel<<<NTOT, 128>>>(x, P, mask, bias, gamma, beta, out, out_size);
}

// round 10
// speedup vs baseline: 2.2930x; 1.0425x over previous
#include <cuda_runtime.h>
#include <cuda_fp16.h>
#include <cstdint>

// ---------------- problem constants ----------------
#define FEA      64
#define NTOT     14112
#define COST_IDX (NTOT * FEA)               /* 903168 */
#define INV_CNT  (1.0f / (14112.0f * 4096.0f))
#define LOG2E    1.4426950408889634f

// W b-fragments, fp16x2 (hi only — 2-term split).
// Flat u32 index t = ((i*4 + ks)*32 + lane)*4 + w  (i,ks<4, lane<32, w<4):
// the 4 uint4 loads per (ks,lane) are lane-consecutive -> coalesced.
// Word (i,w): idx16 = i*4+w = nt*2+r. K-PERMUTED to match float4 A loads:
//   k_orig = 16*ks + 4*(lane&3) + 2*r + {0,1}
__device__ unsigned g_Bfh[2048];

// ---------------- helpers ----------------
// split (x,y) into packed fp16x2 hi (lo16=x) + fp16x2 lo residual
__device__ __forceinline__ void cvtpair(float x, float y, uint32_t& h, uint32_t& l) {
    __half2 hh = __floats2half2_rn(x, y);
    h = *(uint32_t*)&hh;
    float2 hf = __half22float2(hh);
    __half2 ll = __floats2half2_rn(x - hf.x, y - hf.y);
    l = *(uint32_t*)&ll;
}

__device__ __forceinline__ float ex2f(float a) {
    float r;
    asm("ex2.approx.f32 %0, %1;" : "=f"(r) : "f"(a));
    return r;
}

#define MMA_F16(d, a, b) \
    asm volatile("mma.sync.aligned.m16n8k16.row.col.f32.f16.f16.f32 " \
                 "{%0,%1,%2,%3},{%4,%5,%6,%7},{%8,%9},{%0,%1,%2,%3};" \
                 : "+f"((d)[0]), "+f"((d)[1]), "+f"((d)[2]), "+f"((d)[3]) \
                 : "r"((a)[0]), "r"((a)[1]), "r"((a)[2]), "r"((a)[3]), \
                   "r"((b)[0]), "r"((b)[1]))

// ---------------- prep: W -> fp16 b-fragment table (permuted k) ------------
__global__ void ot_prep_kernel(const float* __restrict__ W,
                               float* __restrict__ out, int out_size) {
    int t = blockIdx.x * blockDim.x + threadIdx.x;   // 0..2047
    if (t < 2048) {
        int w    = t & 3;
        int lane = (t >> 2) & 31;
        int ks   = (t >> 7) & 3;
        int i    = t >> 9;
        int idx16 = i * 4 + w;        // nt*2 + r
        int nt   = idx16 >> 1;
        int r    = idx16 & 1;
        int nn   = (lane >> 2) + 8 * nt;                       // B col (output h)
        int k    = 16 * ks + ((lane & 3) << 2) + (r << 1);     // permuted k
        __half2 hh = __floats2half2_rn(W[nn * 64 + k], W[nn * 64 + k + 1]);
        g_Bfh[t] = *(uint32_t*)&hh;
    }
    if (t == 0)
        for (int i = COST_IDX; i < out_size; ++i) out[i] = 0.0f;
}

// ---------------- main kernel: 1 CTA / problem, register-resident ----------
__global__ void __launch_bounds__(128, 8)
ot_mma_kernel(const float* __restrict__ x, const float* __restrict__ P,
              const float* __restrict__ mask, const float* __restrict__ bias,
              const float* __restrict__ gamma, const float* __restrict__ beta,
              float* __restrict__ out, int out_size) {

    __shared__ float txbuf[4][64];
    __shared__ float cred[4];

    const int n    = blockIdx.x;
    const int tid  = threadIdx.x;
    const int lane = tid & 31;
    const int wid  = tid >> 5;
    const int q    = lane >> 2;          // group id 0..7
    const int tg   = lane & 3;           // thread-in-group
    const int c2   = tg << 1;            // col pair base

    // n -> (b, v, p); x/out row base
    const int bb = n / (21 * 42);
    const int rm = n - bb * (21 * 42);
    const int vv = rm / 42;
    const int pp = rm - vv * 42;
    const size_t xob = ((size_t)(bb * 42 + pp) * 21 + vv) * FEA;

    const int fA = 16 * wid + q;         // this thread's two M rows
    const int fB = fA + 8;

    // ---- hoisted DRAM-latency loads: x row values + mask row ----
    const float xfA = x[xob + fA];
    const float xfB = x[xob + fB];
    float2 ms2[8];
    {
        const float2* m2 = (const float2*)(mask + (size_t)n * FEA);
#pragma unroll
        for (int nt = 0; nt < 8; ++nt) ms2[nt] = m2[4 * nt + tg];
    }

    // ---- A fragments: one float4 per row per 16-k chunk (permuted k) ----
    const float4* P4 = (const float4*)(P + ((size_t)n << 12));
    uint32_t ahA[4][2], alA[4][2], ahB[4][2], alB[4][2];   // [chunk][lo/hi word]
    {
        const int baseA = fA * 16 + tg;
        const int baseB = fB * 16 + tg;
#pragma unroll
        for (int j = 0; j < 4; ++j) {
            float4 ua = P4[baseA + 4 * j];
            float4 ub = P4[baseB + 4 * j];
            cvtpair(ua.x, ua.y, ahA[j][0], alA[j][0]);
            cvtpair(ua.z, ua.w, ahA[j][1], alA[j][1]);
            cvtpair(ub.x, ub.y, ahB[j][0], alB[j][0]);
            cvtpair(ub.z, ub.w, ahB[j][1], alB[j][1]);
        }
    }

    // ---- GEMM: 64 HMMA (2-term fp16 split), B streamed per k-step ----
    float acc[8][4];
#pragma unroll
    for (int nt = 0; nt < 8; ++nt)
#pragma unroll
        for (int j = 0; j < 4; ++j) acc[nt][j] = 0.f;

#pragma unroll
    for (int ks = 0; ks < 4; ++ks) {
        // de-aliased B fragment words: pure SSA, no pointer casts on locals
        uint32_t bw[16];
#pragma unroll
        for (int i = 0; i < 4; ++i) {
            uint4 v = ((const uint4*)g_Bfh)[(i * 4 + ks) * 32 + lane];
            bw[4*i + 0] = v.x;
            bw[4*i + 1] = v.y;
            bw[4*i + 2] = v.z;
            bw[4*i + 3] = v.w;
        }

        uint32_t ah[4] = { ahA[ks][0], ahB[ks][0], ahA[ks][1], ahB[ks][1] };
        uint32_t al[4] = { alA[ks][0], alB[ks][0], alA[ks][1], alB[ks][1] };

#pragma unroll
        for (int nt = 0; nt < 8; ++nt) {
            uint32_t bfh[2] = { bw[2*nt], bw[2*nt+1] };
            MMA_F16(acc[nt], ah, bfh);   // Phi * Whi
            MMA_F16(acc[nt], al, bfh);   // Plo * Whi
        }
    }

    // ---- per-column params (L1/L2-hot, short latency) ----
    float2 bias2[8], gam2[8], bet2[8];
    {
        const float2* b2 = (const float2*)bias;
        const float2* g2 = (const float2*)gamma;
        const float2* e2 = (const float2*)beta;
#pragma unroll
        for (int nt = 0; nt < 8; ++nt) {
            int ix = 4 * nt + tg;
            bias2[nt] = b2[ix]; gam2[nt] = g2[ix]; bet2[nt] = e2[ix];
        }
    }

    // ---- bias + LN stats (rows fA, fB live in this quad) ----
    float vA[16], vB[16];
    float s1A = 0.f, s2A = 0.f, s1B = 0.f, s2B = 0.f;
#pragma unroll
    for (int nt = 0; nt < 8; ++nt) {
        float a0 = acc[nt][0] + bias2[nt].x;
        float a1 = acc[nt][1] + bias2[nt].y;
        float b0 = acc[nt][2] + bias2[nt].x;
        float b1 = acc[nt][3] + bias2[nt].y;
        vA[2*nt] = a0; vA[2*nt+1] = a1;
        vB[2*nt] = b0; vB[2*nt+1] = b1;
        s1A += a0 + a1; s2A += a0*a0 + a1*a1;
        s1B += b0 + b1; s2B += b0*b0 + b1*b1;
    }
#pragma unroll
    for (int m = 1; m <= 2; m <<= 1) {
        s1A += __shfl_xor_sync(0xffffffffu, s1A, m);
        s2A += __shfl_xor_sync(0xffffffffu, s2A, m);
        s1B += __shfl_xor_sync(0xffffffffu, s1B, m);
        s2B += __shfl_xor_sync(0xffffffffu, s2B, m);
    }
    const float muA = s1A * (1.0f/64.0f);
    const float muB = s1B * (1.0f/64.0f);
    const float rsA = rsqrtf(s2A * (1.0f/64.0f) - muA*muA + 1e-5f);
    const float rsB = rsqrtf(s2B * (1.0f/64.0f) - muB*muB + 1e-5f);
    const float nmrA = -muA * rsA;       // z = (v*rsA + nmrA)*gamma + beta
    const float nmrB = -muB * rsB;

    // ---- LN affine (2 FFMA) + exp WITHOUT max subtraction ----
    // |(v-mu)*rs| <= 8 since sum of squares of normalized row == 64*var/(var+eps);
    // with this problem's gamma/beta, exp(z) <= ~e^8 — safe in fp32, softmax
    // is shift-invariant so the result is mathematically identical.
    float sA = 0.f, sB = 0.f;
#pragma unroll
    for (int nt = 0; nt < 8; ++nt) {
        float tA0 = fmaf(vA[2*nt],   rsA, nmrA);
        float tA1 = fmaf(vA[2*nt+1], rsA, nmrA);
        float tB0 = fmaf(vB[2*nt],   rsB, nmrB);
        float tB1 = fmaf(vB[2*nt+1], rsB, nmrB);
        float eA0 = ex2f(fmaf(tA0, gam2[nt].x, bet2[nt].x) * LOG2E);
        float eA1 = ex2f(fmaf(tA1, gam2[nt].y, bet2[nt].y) * LOG2E);
        float eB0 = ex2f(fmaf(tB0, gam2[nt].x, bet2[nt].x) * LOG2E);
        float eB1 = ex2f(fmaf(tB1, gam2[nt].y, bet2[nt].y) * LOG2E);
        vA[2*nt] = eA0; vA[2*nt+1] = eA1;
        vB[2*nt] = eB0; vB[2*nt+1] = eB1;
        sA += eA0 + eA1; sB += eB0 + eB1;
    }
#pragma unroll
    for (int m = 1; m <= 2; m <<= 1) {
        sA += __shfl_xor_sync(0xffffffffu, sA, m);
        sB += __shfl_xor_sync(0xffffffffu, sB, m);
    }
    const float invA = __fdividef(1.0f, sA);
    const float invB = __fdividef(1.0f, sB);
    const float sclA = xfA * invA;       // transport scale, normalization folded
    const float sclB = xfB * invB;

    // ---- cost dot (unnormalized) + transport partials ----
    float dotA = 0.f, dotB = 0.f;
    float t[16];
#pragma unroll
    for (int nt = 0; nt < 8; ++nt) {
        dotA = fmaf(vA[2*nt], ms2[nt].x, fmaf(vA[2*nt+1], ms2[nt].y, dotA));
        dotB = fmaf(vB[2*nt], ms2[nt].x, fmaf(vB[2*nt+1], ms2[nt].y, dotB));
        t[2*nt]   = fmaf(vA[2*nt],   sclA, vB[2*nt]   * sclB);
        t[2*nt+1] = fmaf(vA[2*nt+1], sclA, vB[2*nt+1] * sclB);
    }
    float costp = fmaf(dotA, invA, dotB * invB);

    // ---- transport: reduce-scatter over the 8 quads (14 shuffles) ----
    // final owner: thread (q,tg) holds cols 8q+2tg, 8q+2tg+1
    {
        const bool hi4 = (q & 4) != 0;
        float u[8];
#pragma unroll
        for (int j = 0; j < 8; ++j) {
            float send = hi4 ? t[j] : t[8 + j];
            float recv = __shfl_xor_sync(0xffffffffu, send, 16);
            u[j] = (hi4 ? t[8 + j] : t[j]) + recv;
        }
        const bool hi2 = (q & 2) != 0;
        float v[4];
#pragma unroll
        for (int j = 0; j < 4; ++j) {
            float send = hi2 ? u[j] : u[4 + j];
            float recv = __shfl_xor_sync(0xffffffffu, send, 8);
            v[j] = (hi2 ? u[4 + j] : u[j]) + recv;
        }
        const bool hi1 = (q & 1) != 0;
        float s0 = hi1 ? v[0] : v[2];
        float r0 = __shfl_xor_sync(0xffffffffu, s0, 4);
        float w0 = (hi1 ? v[2] : v[0]) + r0;
        float s1 = hi1 ? v[1] : v[3];
        float r1 = __shfl_xor_sync(0xffffffffu, s1, 4);
        float w1 = (hi1 ? v[3] : v[1]) + r1;
        *(float2*)&txbuf[wid][8 * q + c2] = make_float2(w0, w1);
    }

    // ---- cost warp reduce ----
#pragma unroll
    for (int m = 1; m <= 16; m <<= 1)
        costp += __shfl_xor_sync(0xffffffffu, costp, m);
    if (lane == 0) cred[wid] = costp;
    __syncthreads();

    // ---- combine warps: output row + cost atomic ----
    if (tid < FEA)
        out[xob + tid] = (txbuf[0][tid] + txbuf[1][tid])
                       + (txbuf[2][tid] + txbuf[3][tid]);
    if (tid == 0 && out_size > COST_IDX)
        atomicAdd(&out[COST_IDX], (cred[0] + cred[1] + cred[2] + cred[3]) * INV_CNT);
}

extern "C" void kernel_launch(void* const* d_in, const int* in_sizes, int n_in,
                              void* d_out, int out_size) {
    const float* x     = (const float*)d_in[0];
    const float* P     = (const float*)d_in[1];
    const float* mask  = (const float*)d_in[2];
    const float* W     = (const float*)d_in[3];
    const float* bias  = (const float*)d_in[4];
    const float* gamma = (const float*)d_in[5];
    const float* beta  = (const float*)d_in[6];
    float* out = (float*)d_out;

    ot_prep_kernel<<<8, 256>>>(W, out, out_size);
    ot_mma_kernel<<<NTOT, 128>>>(x, P, mask, bias, gamma, beta, out, out_size);
}

// round 11
// speedup vs baseline: 2.2939x; 1.0004x over previous
#include <cuda_runtime.h>
#include <cuda_fp16.h>
#include <cstdint>

// ---------------- problem constants ----------------
#define FEA      64
#define NTOT     14112
#define COST_IDX (NTOT * FEA)               /* 903168 */
#define INV_CNT  (1.0f / (14112.0f * 4096.0f))
#define LOG2E    1.4426950408889634f

// W b-fragments, fp16x2 (hi only — 2-term split).
// Flat u32 index t = ((i*4 + ks)*32 + lane)*4 + w  (i,ks<4, lane<32, w<4):
// the 4 uint4 loads per (ks,lane) are lane-consecutive -> coalesced.
// Word (i,w): idx16 = i*4+w = nt*2+r. K-PERMUTED to match float4 A loads:
//   k_orig = 16*ks + 4*(lane&3) + 2*r + {0,1}
__device__ unsigned g_Bfh[2048];

// ---------------- helpers ----------------
// split (x,y) into packed fp16x2 hi (lo16=x) + fp16x2 lo residual
__device__ __forceinline__ void cvtpair(float x, float y, uint32_t& h, uint32_t& l) {
    __half2 hh = __floats2half2_rn(x, y);
    h = *(uint32_t*)&hh;
    float2 hf = __half22float2(hh);
    __half2 ll = __floats2half2_rn(x - hf.x, y - hf.y);
    l = *(uint32_t*)&ll;
}

__device__ __forceinline__ float ex2f(float a) {
    float r;
    asm("ex2.approx.f32 %0, %1;" : "=f"(r) : "f"(a));
    return r;
}

#define MMA_F16(d, a, b) \
    asm volatile("mma.sync.aligned.m16n8k16.row.col.f32.f16.f16.f32 " \
                 "{%0,%1,%2,%3},{%4,%5,%6,%7},{%8,%9},{%0,%1,%2,%3};" \
                 : "+f"((d)[0]), "+f"((d)[1]), "+f"((d)[2]), "+f"((d)[3]) \
                 : "r"((a)[0]), "r"((a)[1]), "r"((a)[2]), "r"((a)[3]), \
                   "r"((b)[0]), "r"((b)[1]))

// ---------------- prep: W -> fp16 b-fragment table (permuted k) ------------
__global__ void ot_prep_kernel(const float* __restrict__ W,
                               float* __restrict__ out, int out_size) {
    int t = blockIdx.x * blockDim.x + threadIdx.x;   // 0..2047
    if (t < 2048) {
        int w    = t & 3;
        int lane = (t >> 2) & 31;
        int ks   = (t >> 7) & 3;
        int i    = t >> 9;
        int idx16 = i * 4 + w;        // nt*2 + r
        int nt   = idx16 >> 1;
        int r    = idx16 & 1;
        int nn   = (lane >> 2) + 8 * nt;                       // B col (output h)
        int k    = 16 * ks + ((lane & 3) << 2) + (r << 1);     // permuted k
        __half2 hh = __floats2half2_rn(W[nn * 64 + k], W[nn * 64 + k + 1]);
        g_Bfh[t] = *(uint32_t*)&hh;
    }
    if (t == 0)
        for (int i = COST_IDX; i < out_size; ++i) out[i] = 0.0f;
}

// ---------------- main kernel: 1 CTA / problem, register-resident ----------
__global__ void __launch_bounds__(128, 8)
ot_mma_kernel(const float* __restrict__ x, const float* __restrict__ P,
              const float* __restrict__ mask, const float* __restrict__ bias,
              const float* __restrict__ gamma, const float* __restrict__ beta,
              float* __restrict__ out, int out_size) {

    __shared__ float txbuf[4][64];
    __shared__ float cred[4];

    const int n    = blockIdx.x;
    const int tid  = threadIdx.x;
    const int lane = tid & 31;
    const int wid  = tid >> 5;
    const int q    = lane >> 2;          // group id 0..7
    const int tg   = lane & 3;           // thread-in-group
    const int c2   = tg << 1;            // col pair base

    // n -> (b, v, p); x/out row base
    const int bb = n / (21 * 42);
    const int rm = n - bb * (21 * 42);
    const int vv = rm / 42;
    const int pp = rm - vv * 42;
    const size_t xob = ((size_t)(bb * 42 + pp) * 21 + vv) * FEA;

    const int fA = 16 * wid + q;         // this thread's two M rows
    const int fB = fA + 8;

    // ---- hoisted DRAM-latency loads: x row values + mask row ----
    const float xfA = x[xob + fA];
    const float xfB = x[xob + fB];
    float2 ms2[8];
    {
        const float2* m2 = (const float2*)(mask + (size_t)n * FEA);
#pragma unroll
        for (int nt = 0; nt < 8; ++nt) ms2[nt] = m2[4 * nt + tg];
    }

    // ---- A fragments: one float4 per row per 16-k chunk (permuted k) ----
    const float4* P4 = (const float4*)(P + ((size_t)n << 12));
    uint32_t ahA[4][2], alA[4][2], ahB[4][2], alB[4][2];   // [chunk][lo/hi word]
    {
        const int baseA = fA * 16 + tg;
        const int baseB = fB * 16 + tg;
#pragma unroll
        for (int j = 0; j < 4; ++j) {
            float4 ua = P4[baseA + 4 * j];
            float4 ub = P4[baseB + 4 * j];
            cvtpair(ua.x, ua.y, ahA[j][0], alA[j][0]);
            cvtpair(ua.z, ua.w, ahA[j][1], alA[j][1]);
            cvtpair(ub.x, ub.y, ahB[j][0], alB[j][0]);
            cvtpair(ub.z, ub.w, ahB[j][1], alB[j][1]);
        }
    }

    // ---- GEMM: 64 HMMA (2-term fp16 split), B streamed per k-step ----
    float acc[8][4];
#pragma unroll
    for (int nt = 0; nt < 8; ++nt)
#pragma unroll
        for (int j = 0; j < 4; ++j) acc[nt][j] = 0.f;

#pragma unroll
    for (int ks = 0; ks < 4; ++ks) {
        // de-aliased B fragment words: pure SSA, no pointer casts on locals
        uint32_t bw[16];
#pragma unroll
        for (int i = 0; i < 4; ++i) {
            uint4 v = ((const uint4*)g_Bfh)[(i * 4 + ks) * 32 + lane];
            bw[4*i + 0] = v.x;
            bw[4*i + 1] = v.y;
            bw[4*i + 2] = v.z;
            bw[4*i + 3] = v.w;
        }

        uint32_t ah[4] = { ahA[ks][0], ahB[ks][0], ahA[ks][1], ahB[ks][1] };
        uint32_t al[4] = { alA[ks][0], alB[ks][0], alA[ks][1], alB[ks][1] };

#pragma unroll
        for (int nt = 0; nt < 8; ++nt) {
            uint32_t bfh[2] = { bw[2*nt], bw[2*nt+1] };
            MMA_F16(acc[nt], ah, bfh);   // Phi * Whi
            MMA_F16(acc[nt], al, bfh);   // Plo * Whi
        }
    }

    // ---- per-column params (L1/L2-hot, short latency) ----
    float2 bias2[8], gam2[8], bet2[8];
    {
        const float2* b2 = (const float2*)bias;
        const float2* g2 = (const float2*)gamma;
        const float2* e2 = (const float2*)beta;
#pragma unroll
        for (int nt = 0; nt < 8; ++nt) {
            int ix = 4 * nt + tg;
            bias2[nt] = b2[ix]; gam2[nt] = g2[ix]; bet2[nt] = e2[ix];
        }
    }

    // ---- bias + LN stats (rows fA, fB live in this quad) ----
    float vA[16], vB[16];
    float s1A = 0.f, s2A = 0.f, s1B = 0.f, s2B = 0.f;
#pragma unroll
    for (int nt = 0; nt < 8; ++nt) {
        float a0 = acc[nt][0] + bias2[nt].x;
        float a1 = acc[nt][1] + bias2[nt].y;
        float b0 = acc[nt][2] + bias2[nt].x;
        float b1 = acc[nt][3] + bias2[nt].y;
        vA[2*nt] = a0; vA[2*nt+1] = a1;
        vB[2*nt] = b0; vB[2*nt+1] = b1;
        s1A += a0 + a1; s2A += a0*a0 + a1*a1;
        s1B += b0 + b1; s2B += b0*b0 + b1*b1;
    }
#pragma unroll
    for (int m = 1; m <= 2; m <<= 1) {
        s1A += __shfl_xor_sync(0xffffffffu, s1A, m);
        s2A += __shfl_xor_sync(0xffffffffu, s2A, m);
        s1B += __shfl_xor_sync(0xffffffffu, s1B, m);
        s2B += __shfl_xor_sync(0xffffffffu, s2B, m);
    }
    const float muA = s1A * (1.0f/64.0f);
    const float muB = s1B * (1.0f/64.0f);
    const float rsA = rsqrtf(s2A * (1.0f/64.0f) - muA*muA + 1e-5f);
    const float rsB = rsqrtf(s2B * (1.0f/64.0f) - muB*muB + 1e-5f);
    const float nmrA = -muA * rsA;       // z = (v*rsA + nmrA)*gamma + beta
    const float nmrB = -muB * rsB;

    // ---- LN affine (2 FFMA) + exp WITHOUT max subtraction ----
    // |(v-mu)*rs| <= 8 since sum of squares of normalized row == 64*var/(var+eps);
    // with this problem's gamma/beta, exp(z) <= ~e^8 — safe in fp32, softmax
    // is shift-invariant so the result is mathematically identical.
    float sA = 0.f, sB = 0.f;
#pragma unroll
    for (int nt = 0; nt < 8; ++nt) {
        float tA0 = fmaf(vA[2*nt],   rsA, nmrA);
        float tA1 = fmaf(vA[2*nt+1], rsA, nmrA);
        float tB0 = fmaf(vB[2*nt],   rsB, nmrB);
        float tB1 = fmaf(vB[2*nt+1], rsB, nmrB);
        float eA0 = ex2f(fmaf(tA0, gam2[nt].x, bet2[nt].x) * LOG2E);
        float eA1 = ex2f(fmaf(tA1, gam2[nt].y, bet2[nt].y) * LOG2E);
        float eB0 = ex2f(fmaf(tB0, gam2[nt].x, bet2[nt].x) * LOG2E);
        float eB1 = ex2f(fmaf(tB1, gam2[nt].y, bet2[nt].y) * LOG2E);
        vA[2*nt] = eA0; vA[2*nt+1] = eA1;
        vB[2*nt] = eB0; vB[2*nt+1] = eB1;
        sA += eA0 + eA1; sB += eB0 + eB1;
    }
#pragma unroll
    for (int m = 1; m <= 2; m <<= 1) {
        sA += __shfl_xor_sync(0xffffffffu, sA, m);
        sB += __shfl_xor_sync(0xffffffffu, sB, m);
    }
    const float invA = __fdividef(1.0f, sA);
    const float invB = __fdividef(1.0f, sB);
    const float sclA = xfA * invA;       // transport scale, normalization folded
    const float sclB = xfB * invB;

    // ---- cost dot (unnormalized) + transport partials ----
    float dotA = 0.f, dotB = 0.f;
    float t[16];
#pragma unroll
    for (int nt = 0; nt < 8; ++nt) {
        dotA = fmaf(vA[2*nt], ms2[nt].x, fmaf(vA[2*nt+1], ms2[nt].y, dotA));
        dotB = fmaf(vB[2*nt], ms2[nt].x, fmaf(vB[2*nt+1], ms2[nt].y, dotB));
        t[2*nt]   = fmaf(vA[2*nt],   sclA, vB[2*nt]   * sclB);
        t[2*nt+1] = fmaf(vA[2*nt+1], sclA, vB[2*nt+1] * sclB);
    }
    float costp = fmaf(dotA, invA, dotB * invB);

    // ---- transport: reduce-scatter over the 8 quads (14 shuffles) ----
    // final owner: thread (q,tg) holds cols 8q+2tg, 8q+2tg+1
    {
        const bool hi4 = (q & 4) != 0;
        float u[8];
#pragma unroll
        for (int j = 0; j < 8; ++j) {
            float send = hi4 ? t[j] : t[8 + j];
            float recv = __shfl_xor_sync(0xffffffffu, send, 16);
            u[j] = (hi4 ? t[8 + j] : t[j]) + recv;
        }
        const bool hi2 = (q & 2) != 0;
        float v[4];
#pragma unroll
        for (int j = 0; j < 4; ++j) {
            float send = hi2 ? u[j] : u[4 + j];
            float recv = __shfl_xor_sync(0xffffffffu, send, 8);
            v[j] = (hi2 ? u[4 + j] : u[j]) + recv;
        }
        const bool hi1 = (q & 1) != 0;
        float s0 = hi1 ? v[0] : v[2];
        float r0 = __shfl_xor_sync(0xffffffffu, s0, 4);
        float w0 = (hi1 ? v[2] : v[0]) + r0;
        float s1 = hi1 ? v[1] : v[3];
        float r1 = __shfl_xor_sync(0xffffffffu, s1, 4);
        float w1 = (hi1 ? v[3] : v[1]) + r1;
        *(float2*)&txbuf[wid][8 * q + c2] = make_float2(w0, w1);
    }

    // ---- cost warp reduce ----
#pragma unroll
    for (int m = 1; m <= 16; m <<= 1)
        costp += __shfl_xor_sync(0xffffffffu, costp, m);
    if (lane == 0) cred[wid] = costp;
    __syncthreads();

    // ---- combine warps: output row + cost atomic ----
    if (tid < FEA)
        out[xob + tid] = (txbuf[0][tid] + txbuf[1][tid])
                       + (txbuf[2][tid] + txbuf[3][tid]);
    if (tid == 0 && out_size > COST_IDX)
        atomicAdd(&out[COST_IDX], (cred[0] + cred[1] + cred[2] + cred[3]) * INV_CNT);
}

extern "C" void kernel_launch(void* const* d_in, const int* in_sizes, int n_in,
                              void* d_out, int out_size) {
    const float* x     = (const float*)d_in[0];
    const float* P     = (const float*)d_in[1];
    const float* mask  = (const float*)d_in[2];
    const float* W     = (const float*)d_in[3];
    const float* bias  = (const float*)d_in[4];
    const float* gamma = (const float*)d_in[5];
    const float* beta  = (const float*)d_in[6];
    float* out = (float*)d_out;

    ot_prep_kernel<<<8, 256>>>(W, out, out_size);
    ot_mma_kernel<<<NTOT, 128>>>(x, P, mask, bias, gamma, beta, out, out_size);
}

// round 13
// speedup vs baseline: 2.5829x; 1.1259x over previous
#include <cuda_runtime.h>
#include <cuda_fp16.h>
#include <cstdint>

// ---------------- problem constants ----------------
#define FEA      64
#define NTOT     14112
#define COST_IDX (NTOT * FEA)               /* 903168 */
#define INV_CNT  (1.0f / (14112.0f * 4096.0f))
#define LOG2E    1.4426950408889634f

// W b-fragments, fp16x2 (single-term fp16 GEMM).
// Flat u32 index t = ((i*4 + ks)*32 + lane)*4 + w  (i,ks<4, lane<32, w<4):
// the 4 uint4 loads per (ks,lane) are lane-consecutive -> coalesced.
// Word (i,w): idx16 = i*4+w = nt*2+r. K-PERMUTED to match float4 A loads:
//   k_orig = 16*ks + 4*(lane&3) + 2*r + {0,1}
__device__ unsigned g_Bfh[2048];

// ---------------- helpers ----------------
__device__ __forceinline__ uint32_t packh2(float x, float y) {
    __half2 hh = __floats2half2_rn(x, y);
    return *(uint32_t*)&hh;
}

__device__ __forceinline__ float ex2f(float a) {
    float r;
    asm("ex2.approx.f32 %0, %1;" : "=f"(r) : "f"(a));
    return r;
}

#define MMA_F16(d, a, b) \
    asm volatile("mma.sync.aligned.m16n8k16.row.col.f32.f16.f16.f32 " \
                 "{%0,%1,%2,%3},{%4,%5,%6,%7},{%8,%9},{%0,%1,%2,%3};" \
                 : "+f"((d)[0]), "+f"((d)[1]), "+f"((d)[2]), "+f"((d)[3]) \
                 : "r"((a)[0]), "r"((a)[1]), "r"((a)[2]), "r"((a)[3]), \
                   "r"((b)[0]), "r"((b)[1]))

// ---------------- prep: W -> fp16 b-fragment table (permuted k) ------------
__global__ void ot_prep_kernel(const float* __restrict__ W,
                               float* __restrict__ out, int out_size) {
    int t = blockIdx.x * blockDim.x + threadIdx.x;   // 0..2047
    if (t < 2048) {
        int w    = t & 3;
        int lane = (t >> 2) & 31;
        int ks   = (t >> 7) & 3;
        int i    = t >> 9;
        int idx16 = i * 4 + w;        // nt*2 + r
        int nt   = idx16 >> 1;
        int r    = idx16 & 1;
        int nn   = (lane >> 2) + 8 * nt;                       // B col (output h)
        int k    = 16 * ks + ((lane & 3) << 2) + (r << 1);     // permuted k
        __half2 hh = __floats2half2_rn(W[nn * 64 + k], W[nn * 64 + k + 1]);
        g_Bfh[t] = *(uint32_t*)&hh;
    }
    if (t == 0)
        for (int i = COST_IDX; i < out_size; ++i) out[i] = 0.0f;
}

// ---------------- main kernel: 1 CTA / problem, register-resident ----------
__global__ void __launch_bounds__(128, 8)
ot_mma_kernel(const float* __restrict__ x, const float* __restrict__ P,
              const float* __restrict__ mask, const float* __restrict__ bias,
              const float* __restrict__ gamma, const float* __restrict__ beta,
              float* __restrict__ out, int out_size) {

    __shared__ float txbuf[4][64];
    __shared__ float cred[4];

    const int n    = blockIdx.x;
    const int tid  = threadIdx.x;
    const int lane = tid & 31;
    const int wid  = tid >> 5;
    const int q    = lane >> 2;          // group id 0..7
    const int tg   = lane & 3;           // thread-in-group
    const int c2   = tg << 1;            // col pair base

    // n -> (b, v, p); x/out row base
    const int bb = n / (21 * 42);
    const int rm = n - bb * (21 * 42);
    const int vv = rm / 42;
    const int pp = rm - vv * 42;
    const size_t xob = ((size_t)(bb * 42 + pp) * 21 + vv) * FEA;

    const int fA = 16 * wid + q;         // this thread's two M rows
    const int fB = fA + 8;

    // ---- hoisted DRAM-latency loads: x row values + mask row ----
    const float xfA = x[xob + fA];
    const float xfB = x[xob + fB];
    float2 ms2[8];
    {
        const float2* m2 = (const float2*)(mask + (size_t)n * FEA);
#pragma unroll
        for (int nt = 0; nt < 8; ++nt) ms2[nt] = m2[4 * nt + tg];
    }

    // ---- A fragments: one float4 per row per 16-k chunk (permuted k),
    //      packed straight to fp16x2 (no residual computation) ----
    const float4* P4 = (const float4*)(P + ((size_t)n << 12));
    uint32_t ahA[4][2], ahB[4][2];       // [chunk][lo/hi word]
    {
        const int baseA = fA * 16 + tg;
        const int baseB = fB * 16 + tg;
#pragma unroll
        for (int j = 0; j < 4; ++j) {
            float4 ua = P4[baseA + 4 * j];
            float4 ub = P4[baseB + 4 * j];
            ahA[j][0] = packh2(ua.x, ua.y);
            ahA[j][1] = packh2(ua.z, ua.w);
            ahB[j][0] = packh2(ub.x, ub.y);
            ahB[j][1] = packh2(ub.z, ub.w);
        }
    }

    // ---- GEMM: 32 HMMA (single-term fp16), B streamed per k-step ----
    float acc[8][4];
#pragma unroll
    for (int nt = 0; nt < 8; ++nt)
#pragma unroll
        for (int j = 0; j < 4; ++j) acc[nt][j] = 0.f;

#pragma unroll
    for (int ks = 0; ks < 4; ++ks) {
        uint32_t bw[16];
#pragma unroll
        for (int i = 0; i < 4; ++i) {
            uint4 v = ((const uint4*)g_Bfh)[(i * 4 + ks) * 32 + lane];
            bw[4*i + 0] = v.x;
            bw[4*i + 1] = v.y;
            bw[4*i + 2] = v.z;
            bw[4*i + 3] = v.w;
        }

        uint32_t ah[4] = { ahA[ks][0], ahB[ks][0], ahA[ks][1], ahB[ks][1] };

#pragma unroll
        for (int nt = 0; nt < 8; ++nt) {
            uint32_t bfh[2] = { bw[2*nt], bw[2*nt+1] };
            MMA_F16(acc[nt], ah, bfh);
        }
    }

    // ---- per-column params (L1/L2-hot, short latency) ----
    float2 bias2[8], gam2[8], bet2[8];
    {
        const float2* b2 = (const float2*)bias;
        const float2* g2 = (const float2*)gamma;
        const float2* e2 = (const float2*)beta;
#pragma unroll
        for (int nt = 0; nt < 8; ++nt) {
            int ix = 4 * nt + tg;
            bias2[nt] = b2[ix]; gam2[nt] = g2[ix]; bet2[nt] = e2[ix];
        }
    }

    // ---- bias + LN stats (rows fA, fB live in this quad) ----
    float vA[16], vB[16];
    float s1A = 0.f, s2A = 0.f, s1B = 0.f, s2B = 0.f;
#pragma unroll
    for (int nt = 0; nt < 8; ++nt) {
        float a0 = acc[nt][0] + bias2[nt].x;
        float a1 = acc[nt][1] + bias2[nt].y;
        float b0 = acc[nt][2] + bias2[nt].x;
        float b1 = acc[nt][3] + bias2[nt].y;
        vA[2*nt] = a0; vA[2*nt+1] = a1;
        vB[2*nt] = b0; vB[2*nt+1] = b1;
        s1A += a0 + a1; s2A += a0*a0 + a1*a1;
        s1B += b0 + b1; s2B += b0*b0 + b1*b1;
    }
#pragma unroll
    for (int m = 1; m <= 2; m <<= 1) {
        s1A += __shfl_xor_sync(0xffffffffu, s1A, m);
        s2A += __shfl_xor_sync(0xffffffffu, s2A, m);
        s1B += __shfl_xor_sync(0xffffffffu, s1B, m);
        s2B += __shfl_xor_sync(0xffffffffu, s2B, m);
    }
    const float muA = s1A * (1.0f/64.0f);
    const float muB = s1B * (1.0f/64.0f);
    const float rsA = rsqrtf(s2A * (1.0f/64.0f) - muA*muA + 1e-5f);
    const float rsB = rsqrtf(s2B * (1.0f/64.0f) - muB*muB + 1e-5f);
    const float nmrA = -muA * rsA;       // z = (v*rsA + nmrA)*gamma + beta
    const float nmrB = -muB * rsB;

    // ---- LN affine (2 FFMA) + exp WITHOUT max subtraction ----
    // |(v-mu)*rs| <= 8 (normalized row has bounded L2 norm); exp(z) <= ~e^8,
    // safe in fp32; softmax is shift-invariant so the result is identical.
    float sA = 0.f, sB = 0.f;
#pragma unroll
    for (int nt = 0; nt < 8; ++nt) {
        float tA0 = fmaf(vA[2*nt],   rsA, nmrA);
        float tA1 = fmaf(vA[2*nt+1], rsA, nmrA);
        float tB0 = fmaf(vB[2*nt],   rsB, nmrB);
        float tB1 = fmaf(vB[2*nt+1], rsB, nmrB);
        float eA0 = ex2f(fmaf(tA0, gam2[nt].x, bet2[nt].x) * LOG2E);
        float eA1 = ex2f(fmaf(tA1, gam2[nt].y, bet2[nt].y) * LOG2E);
        float eB0 = ex2f(fmaf(tB0, gam2[nt].x, bet2[nt].x) * LOG2E);
        float eB1 = ex2f(fmaf(tB1, gam2[nt].y, bet2[nt].y) * LOG2E);
        vA[2*nt] = eA0; vA[2*nt+1] = eA1;
        vB[2*nt] = eB0; vB[2*nt+1] = eB1;
        sA += eA0 + eA1; sB += eB0 + eB1;
    }
#pragma unroll
    for (int m = 1; m <= 2; m <<= 1) {
        sA += __shfl_xor_sync(0xffffffffu, sA, m);
        sB += __shfl_xor_sync(0xffffffffu, sB, m);
    }
    const float invA = __fdividef(1.0f, sA);
    const float invB = __fdividef(1.0f, sB);
    const float sclA = xfA * invA;       // transport scale, normalization folded
    const float sclB = xfB * invB;

    // ---- cost dot (unnormalized) + transport partials ----
    float dotA = 0.f, dotB = 0.f;
    float t[16];
#pragma unroll
    for (int nt = 0; nt < 8; ++nt) {
        dotA = fmaf(vA[2*nt], ms2[nt].x, fmaf(vA[2*nt+1], ms2[nt].y, dotA));
        dotB = fmaf(vB[2*nt], ms2[nt].x, fmaf(vB[2*nt+1], ms2[nt].y, dotB));
        t[2*nt]   = fmaf(vA[2*nt],   sclA, vB[2*nt]   * sclB);
        t[2*nt+1] = fmaf(vA[2*nt+1], sclA, vB[2*nt+1] * sclB);
    }
    float costp = fmaf(dotA, invA, dotB * invB);

    // ---- transport: reduce-scatter over the 8 quads (14 shuffles) ----
    // final owner: thread (q,tg) holds cols 8q+2tg, 8q+2tg+1
    {
        const bool hi4 = (q & 4) != 0;
        float u[8];
#pragma unroll
        for (int j = 0; j < 8; ++j) {
            float send = hi4 ? t[j] : t[8 + j];
            float recv = __shfl_xor_sync(0xffffffffu, send, 16);
            u[j] = (hi4 ? t[8 + j] : t[j]) + recv;
        }
        const bool hi2 = (q & 2) != 0;
        float v[4];
#pragma unroll
        for (int j = 0; j < 4; ++j) {
            float send = hi2 ? u[j] : u[4 + j];
            float recv = __shfl_xor_sync(0xffffffffu, send, 8);
            v[j] = (hi2 ? u[4 + j] : u[j]) + recv;
        }
        const bool hi1 = (q & 1) != 0;
        float s0 = hi1 ? v[0] : v[2];
        float r0 = __shfl_xor_sync(0xffffffffu, s0, 4);
        float w0 = (hi1 ? v[2] : v[0]) + r0;
        float s1 = hi1 ? v[1] : v[3];
        float r1 = __shfl_xor_sync(0xffffffffu, s1, 4);
        float w1 = (hi1 ? v[3] : v[1]) + r1;
        *(float2*)&txbuf[wid][8 * q + c2] = make_float2(w0, w1);
    }

    // ---- cost warp reduce ----
#pragma unroll
    for (int m = 1; m <= 16; m <<= 1)
        costp += __shfl_xor_sync(0xffffffffu, costp, m);
    if (lane == 0) cred[wid] = costp;
    __syncthreads();

    // ---- combine warps: output row + cost atomic ----
    if (tid < FEA)
        out[xob + tid] = (txbuf[0][tid] + txbuf[1][tid])
                       + (txbuf[2][tid] + txbuf[3][tid]);
    if (tid == 0 && out_size > COST_IDX)
        atomicAdd(&out[COST_IDX], (cred[0] + cred[1] + cred[2] + cred[3]) * INV_CNT);
}

extern "C" void kernel_launch(void* const* d_in, const int* in_sizes, int n_in,
                              void* d_out, int out_size) {
    const float* x     = (const float*)d_in[0];
    const float* P     = (const float*)d_in[1];
    const float* mask  = (const float*)d_in[2];
    const float* W     = (const float*)d_in[3];
    const float* bias  = (const float*)d_in[4];
    const float* gamma = (const float*)d_in[5];
    const float* beta  = (const float*)d_in[6];
    float* out = (float*)d_out;

    ot_prep_kernel<<<8, 256>>>(W, out, out_size);
    ot_mma_kernel<<<NTOT, 128>>>(x, P, mask, bias, gamma, beta, out, out_size);
}

// round 14
// speedup vs baseline: 2.6636x; 1.0313x over previous
#include <cuda_runtime.h>
#include <cuda_fp16.h>
#include <cstdint>

// ---------------- problem constants ----------------
#define FEA      64
#define NTOT     14112
#define COST_IDX (NTOT * FEA)               /* 903168 */
#define INV_CNT  (1.0f / (14112.0f * 4096.0f))
#define LOG2E    1.4426950408889634f

// W b-fragments, fp16x2 (single-term fp16 GEMM).
// Flat u32 index t = ((i*4 + ks)*32 + lane)*4 + w  (i,ks<4, lane<32, w<4):
// the 4 uint4 loads per (ks,lane) are lane-consecutive -> coalesced.
// Word (i,w): idx16 = i*4+w = nt*2+r. K-PERMUTED to match float4 A loads:
//   k_orig = 16*ks + 4*(lane&3) + 2*r + {0,1}
__device__ unsigned g_Bfh[2048];
// LayerNorm affine constants pre-scaled by log2(e): gamma', beta'
__device__ float g_gamL[64];
__device__ float g_betL[64];

// ---------------- helpers ----------------
__device__ __forceinline__ uint32_t packh2(float x, float y) {
    __half2 hh = __floats2half2_rn(x, y);
    return *(uint32_t*)&hh;
}

__device__ __forceinline__ float ex2f(float a) {
    float r;
    asm("ex2.approx.f32 %0, %1;" : "=f"(r) : "f"(a));
    return r;
}

#define MMA_F16(d, a, b) \
    asm volatile("mma.sync.aligned.m16n8k16.row.col.f32.f16.f16.f32 " \
                 "{%0,%1,%2,%3},{%4,%5,%6,%7},{%8,%9},{%0,%1,%2,%3};" \
                 : "+f"((d)[0]), "+f"((d)[1]), "+f"((d)[2]), "+f"((d)[3]) \
                 : "r"((a)[0]), "r"((a)[1]), "r"((a)[2]), "r"((a)[3]), \
                   "r"((b)[0]), "r"((b)[1]))

// ---------------- prep: W -> fp16 b-frag table, gamma'/beta', zero cost ----
__global__ void ot_prep_kernel(const float* __restrict__ W,
                               const float* __restrict__ gamma,
                               const float* __restrict__ beta,
                               float* __restrict__ out, int out_size) {
    int t = blockIdx.x * blockDim.x + threadIdx.x;   // 0..2047
    if (t < 2048) {
        int w    = t & 3;
        int lane = (t >> 2) & 31;
        int ks   = (t >> 7) & 3;
        int i    = t >> 9;
        int idx16 = i * 4 + w;        // nt*2 + r
        int nt   = idx16 >> 1;
        int r    = idx16 & 1;
        int nn   = (lane >> 2) + 8 * nt;                       // B col (output h)
        int k    = 16 * ks + ((lane & 3) << 2) + (r << 1);     // permuted k
        __half2 hh = __floats2half2_rn(W[nn * 64 + k], W[nn * 64 + k + 1]);
        g_Bfh[t] = *(uint32_t*)&hh;
    }
    if (t < 64) {
        g_gamL[t] = gamma[t] * LOG2E;
        g_betL[t] = beta[t]  * LOG2E;
    }
    if (t == 0)
        for (int i = COST_IDX; i < out_size; ++i) out[i] = 0.0f;
}

// ---------------- main kernel: 1 CTA / problem, register-resident ----------
__global__ void __launch_bounds__(128, 8)
ot_mma_kernel(const float* __restrict__ x, const float* __restrict__ P,
              const float* __restrict__ mask, const float* __restrict__ bias,
              const float* __restrict__ gamma, const float* __restrict__ beta,
              float* __restrict__ out, int out_size) {

    __shared__ float txbuf[4][64];
    __shared__ float cred[4];

    const int n    = blockIdx.x;
    const int tid  = threadIdx.x;
    const int lane = tid & 31;
    const int wid  = tid >> 5;
    const int q    = lane >> 2;          // group id 0..7
    const int tg   = lane & 3;           // thread-in-group
    const int c2   = tg << 1;            // col pair base

    // n -> (b, v, p); x/out row base
    const int bb = n / (21 * 42);
    const int rm = n - bb * (21 * 42);
    const int vv = rm / 42;
    const int pp = rm - vv * 42;
    const size_t xob = ((size_t)(bb * 42 + pp) * 21 + vv) * FEA;

    const int fA = 16 * wid + q;         // this thread's two M rows
    const int fB = fA + 8;

    // ---- hoisted x row values (2 regs only) ----
    const float xfA = x[xob + fA];
    const float xfB = x[xob + fB];

    // ---- A fragments: one float4 per row per 16-k chunk (permuted k),
    //      packed straight to fp16x2 ----
    const float4* P4 = (const float4*)(P + ((size_t)n << 12));
    uint32_t ahA[4][2], ahB[4][2];       // [chunk][lo/hi word]
    {
        const int baseA = fA * 16 + tg;
        const int baseB = fB * 16 + tg;
#pragma unroll
        for (int j = 0; j < 4; ++j) {
            float4 ua = P4[baseA + 4 * j];
            float4 ub = P4[baseB + 4 * j];
            ahA[j][0] = packh2(ua.x, ua.y);
            ahA[j][1] = packh2(ua.z, ua.w);
            ahB[j][0] = packh2(ub.x, ub.y);
            ahB[j][1] = packh2(ub.z, ub.w);
        }
    }

    // ---- GEMM: 32 HMMA, B streamed in 8-word halves (low reg pressure) ----
    float acc[8][4];
#pragma unroll
    for (int nt = 0; nt < 8; ++nt)
#pragma unroll
        for (int j = 0; j < 4; ++j) acc[nt][j] = 0.f;

#pragma unroll
    for (int ks = 0; ks < 4; ++ks) {
        uint32_t ah[4] = { ahA[ks][0], ahB[ks][0], ahA[ks][1], ahB[ks][1] };
#pragma unroll
        for (int h = 0; h < 2; ++h) {    // half: i = 2h, 2h+1 -> nt 4h..4h+3
            uint32_t bw[8];
#pragma unroll
            for (int i2 = 0; i2 < 2; ++i2) {
                uint4 v = ((const uint4*)g_Bfh)[((2 * h + i2) * 4 + ks) * 32 + lane];
                bw[4*i2 + 0] = v.x;
                bw[4*i2 + 1] = v.y;
                bw[4*i2 + 2] = v.z;
                bw[4*i2 + 3] = v.w;
            }
#pragma unroll
            for (int j2 = 0; j2 < 4; ++j2) {
                int nt = 4 * h + j2;
                uint32_t bfh[2] = { bw[2*j2], bw[2*j2+1] };
                MMA_F16(acc[nt], ah, bfh);
            }
        }
    }

    // ---- prefetch mask row (DRAM) right after GEMM; stats hide latency ----
    float2 ms2[8];
    {
        const float2* m2 = (const float2*)(mask + (size_t)n * FEA);
#pragma unroll
        for (int nt = 0; nt < 8; ++nt) ms2[nt] = m2[4 * nt + tg];
    }

    // ---- bias + LN stats (bias loaded in-loop, L1-hot) ----
    const float2* b2 = (const float2*)bias;
    float vA[16], vB[16];
    float s1A = 0.f, s2A = 0.f, s1B = 0.f, s2B = 0.f;
#pragma unroll
    for (int nt = 0; nt < 8; ++nt) {
        float2 bv = b2[4 * nt + tg];
        float a0 = acc[nt][0] + bv.x;
        float a1 = acc[nt][1] + bv.y;
        float b0 = acc[nt][2] + bv.x;
        float b1 = acc[nt][3] + bv.y;
        vA[2*nt] = a0; vA[2*nt+1] = a1;
        vB[2*nt] = b0; vB[2*nt+1] = b1;
        s1A += a0 + a1; s2A += a0*a0 + a1*a1;
        s1B += b0 + b1; s2B += b0*b0 + b1*b1;
    }
#pragma unroll
    for (int m = 1; m <= 2; m <<= 1) {
        s1A += __shfl_xor_sync(0xffffffffu, s1A, m);
        s2A += __shfl_xor_sync(0xffffffffu, s2A, m);
        s1B += __shfl_xor_sync(0xffffffffu, s1B, m);
        s2B += __shfl_xor_sync(0xffffffffu, s2B, m);
    }
    const float muA = s1A * (1.0f/64.0f);
    const float muB = s1B * (1.0f/64.0f);
    const float rsA = rsqrtf(s2A * (1.0f/64.0f) - muA*muA + 1e-5f);
    const float rsB = rsqrtf(s2B * (1.0f/64.0f) - muB*muB + 1e-5f);
    const float nmrA = -muA * rsA;       // t = v*rs + nmr
    const float nmrB = -muB * rsB;

    // ---- LN affine + exp: FFMA + FFMA + EX2 (log2e folded into gamma'/beta')
    // No max subtraction: |t| <= 8 so exp(z) <= ~e^8, safe in fp32;
    // softmax is shift-invariant -> identical result.
    const float2* gl2 = (const float2*)g_gamL;
    const float2* el2 = (const float2*)g_betL;
    float sA = 0.f, sB = 0.f;
#pragma unroll
    for (int nt = 0; nt < 8; ++nt) {
        float2 gv = gl2[4 * nt + tg];
        float2 ev = el2[4 * nt + tg];
        float tA0 = fmaf(vA[2*nt],   rsA, nmrA);
        float tA1 = fmaf(vA[2*nt+1], rsA, nmrA);
        float tB0 = fmaf(vB[2*nt],   rsB, nmrB);
        float tB1 = fmaf(vB[2*nt+1], rsB, nmrB);
        float eA0 = ex2f(fmaf(tA0, gv.x, ev.x));
        float eA1 = ex2f(fmaf(tA1, gv.y, ev.y));
        float eB0 = ex2f(fmaf(tB0, gv.x, ev.x));
        float eB1 = ex2f(fmaf(tB1, gv.y, ev.y));
        vA[2*nt] = eA0; vA[2*nt+1] = eA1;
        vB[2*nt] = eB0; vB[2*nt+1] = eB1;
        sA += eA0 + eA1; sB += eB0 + eB1;
    }
#pragma unroll
    for (int m = 1; m <= 2; m <<= 1) {
        sA += __shfl_xor_sync(0xffffffffu, sA, m);
        sB += __shfl_xor_sync(0xffffffffu, sB, m);
    }
    const float invA = __fdividef(1.0f, sA);
    const float invB = __fdividef(1.0f, sB);
    const float sclA = xfA * invA;       // transport scale, normalization folded
    const float sclB = xfB * invB;

    // ---- cost dot (unnormalized) + transport partials ----
    float dotA = 0.f, dotB = 0.f;
    float t[16];
#pragma unroll
    for (int nt = 0; nt < 8; ++nt) {
        dotA = fmaf(vA[2*nt], ms2[nt].x, fmaf(vA[2*nt+1], ms2[nt].y, dotA));
        dotB = fmaf(vB[2*nt], ms2[nt].x, fmaf(vB[2*nt+1], ms2[nt].y, dotB));
        t[2*nt]   = fmaf(vA[2*nt],   sclA, vB[2*nt]   * sclB);
        t[2*nt+1] = fmaf(vA[2*nt+1], sclA, vB[2*nt+1] * sclB);
    }
    float costp = fmaf(dotA, invA, dotB * invB);

    // ---- transport: reduce-scatter over the 8 quads (14 shuffles) ----
    // final owner: thread (q,tg) holds cols 8q+2tg, 8q+2tg+1
    {
        const bool hi4 = (q & 4) != 0;
        float u[8];
#pragma unroll
        for (int j = 0; j < 8; ++j) {
            float send = hi4 ? t[j] : t[8 + j];
            float recv = __shfl_xor_sync(0xffffffffu, send, 16);
            u[j] = (hi4 ? t[8 + j] : t[j]) + recv;
        }
        const bool hi2 = (q & 2) != 0;
        float v[4];
#pragma unroll
        for (int j = 0; j < 4; ++j) {
            float send = hi2 ? u[j] : u[4 + j];
            float recv = __shfl_xor_sync(0xffffffffu, send, 8);
            v[j] = (hi2 ? u[4 + j] : u[j]) + recv;
        }
        const bool hi1 = (q & 1) != 0;
        float s0 = hi1 ? v[0] : v[2];
        float r0 = __shfl_xor_sync(0xffffffffu, s0, 4);
        float w0 = (hi1 ? v[2] : v[0]) + r0;
        float s1 = hi1 ? v[1] : v[3];
        float r1 = __shfl_xor_sync(0xffffffffu, s1, 4);
        float w1 = (hi1 ? v[3] : v[1]) + r1;
        *(float2*)&txbuf[wid][8 * q + c2] = make_float2(w0, w1);
    }

    // ---- cost warp reduce ----
#pragma unroll
    for (int m = 1; m <= 16; m <<= 1)
        costp += __shfl_xor_sync(0xffffffffu, costp, m);
    if (lane == 0) cred[wid] = costp;
    __syncthreads();

    // ---- combine warps: output row + cost atomic ----
    if (tid < FEA)
        out[xob + tid] = (txbuf[0][tid] + txbuf[1][tid])
                       + (txbuf[2][tid] + txbuf[3][tid]);
    if (tid == 0 && out_size > COST_IDX)
        atomicAdd(&out[COST_IDX], (cred[0] + cred[1] + cred[2] + cred[3]) * INV_CNT);
}

extern "C" void kernel_launch(void* const* d_in, const int* in_sizes, int n_in,
                              void* d_out, int out_size) {
    const float* x     = (const float*)d_in[0];
    const float* P     = (const float*)d_in[1];
    const float* mask  = (const float*)d_in[2];
    const float* W     = (const float*)d_in[3];
    const float* bias  = (const float*)d_in[4];
    const float* gamma = (const float*)d_in[5];
    const float* beta  = (const float*)d_in[6];
    float* out = (float*)d_out;

    ot_prep_kernel<<<8, 256>>>(W, gamma, beta, out, out_size);
    ot_mma_kernel<<<NTOT, 128>>>(x, P, mask, bias, gamma, beta, out, out_size);
}